// round 6
// baseline (speedup 1.0000x reference)
#include <cuda_runtime.h>
#include <math.h>

#define N0 50000
#define N1 12500
#define N2 3125
#define NTOT 65625            // N0+N1+N2
#define E0C 800000
#define E1C 200000
#define E2C 50000
#define ETOT 1050000
#define NNZC 200000

// node row offsets per level
#define NB1 50000
#define NB2 62500
// edge offsets
#define EB1 800000
#define EB2 1000000

// -------- fused zeroed scratch region: [agg6 | agg | i1 | i2] --------
#define AGG6_OFF 0
#define AGG_OFF  393752
#define I1_OFF   8793752
#define I2_OFF   13593752
#define ZR_TOT   18393752

__device__ float g_zr[ZR_TOT];
__device__ float g_h1[NTOT * 128];
__device__ float g_e [NTOT * 96];
// pair-interleaved (along k) weight copies
__device__ float g_w1t[3 * 16384];
__device__ float g_w2t[3 * 16384];
__device__ float g_lint[3 * 12288];
__device__ float g_dect[3 * 6144];

static inline int cdiv(int a, int b) { return (a + b - 1) / b; }

// ---------------- f32x2 helpers ----------------
typedef unsigned long long ull;
__device__ __forceinline__ ull pk2(float x, float y) {
    ull r; asm("mov.b64 %0, {%1, %2};" : "=l"(r) : "f"(x), "f"(y)); return r;
}
__device__ __forceinline__ ull fma2(ull a, ull b, ull c) {
    ull d; asm("fma.rn.f32x2 %0, %1, %2, %3;" : "=l"(d) : "l"(a), "l"(b), "l"(c));
    return d;
}
__device__ __forceinline__ float2 up2(ull v) {
    float2 f; asm("mov.b64 {%0, %1}, %2;" : "=f"(f.x), "=f"(f.y) : "l"(v)); return f;
}
__device__ __forceinline__ float hsum2(ull v) { float2 f = up2(v); return f.x + f.y; }

// ---------------- prep: weight repack + scratch zero in one launch ----------------
// repack: Wt[m][f][2] = (W[2m][f], W[2m+1][f])
__global__ void prep_kernel(const float* __restrict__ W1, const float* __restrict__ W2,
                            const float* __restrict__ linW, const float* __restrict__ decW,
                            float* __restrict__ w1t, float* __restrict__ w2t,
                            float* __restrict__ lint, float* __restrict__ dect,
                            float4* __restrict__ zr, int nq) {
    int i = blockIdx.x * blockDim.x + threadIdx.x;
    if (i < nq) zr[i] = make_float4(0.f, 0.f, 0.f, 0.f);
    if (i < 24576) {                       // 3 lvl x 64 m x 128 f
        int lvl = i / 8192, r = i % 8192, m = r / 128, f = r % 128;
        int src = lvl * 16384, dst = lvl * 16384 + m * 256 + f * 2;
        w1t[dst]     = W1[src + (2 * m) * 128 + f];
        w1t[dst + 1] = W1[src + (2 * m + 1) * 128 + f];
        w2t[dst]     = W2[src + (2 * m) * 128 + f];
        w2t[dst + 1] = W2[src + (2 * m + 1) * 128 + f];
    } else if (i < 24576 + 18432) {        // 3 lvl x 64 m x 96 f
        int q = i - 24576;
        int lvl = q / 6144, r = q % 6144, m = r / 96, f = r % 96;
        lint[lvl * 12288 + m * 192 + f * 2]     = linW[lvl * 12288 + (2 * m) * 96 + f];
        lint[lvl * 12288 + m * 192 + f * 2 + 1] = linW[lvl * 12288 + (2 * m + 1) * 96 + f];
    } else if (i < 24576 + 18432 + 9216) { // 3 br x 48 m x 64 h
        int q = i - 43008;
        int br = q / 3072, r = q % 3072, m = r / 64, h = r % 64;
        dect[br * 6144 + m * 128 + h * 2]     = decW[br * 6144 + (2 * m) * 64 + h];
        dect[br * 6144 + m * 128 + h * 2 + 1] = decW[br * 6144 + (2 * m + 1) * 64 + h];
    }
}

// ---------------- kernels ----------------

// stage 1 aggregation: agg6[dst] += x[src] (6 feats), float2 RED
__global__ void scatter6_all(const float* __restrict__ x0, const float* __restrict__ x1,
                             const float* __restrict__ x2,
                             const int* __restrict__ ei0, const int* __restrict__ ei1,
                             const int* __restrict__ ei2,
                             float* __restrict__ agg6) {
    int e = blockIdx.x * blockDim.x + threadIdx.x;
    if (e >= ETOT) return;
    int lvl = (e >= EB1) + (e >= EB2);
    const int* ei;
    const float* x;
    int le, E, nb;
    if (lvl == 0)      { ei = ei0; x = x0; le = e;       E = E0C; nb = 0;   }
    else if (lvl == 1) { ei = ei1; x = x1; le = e - EB1; E = E1C; nb = NB1; }
    else               { ei = ei2; x = x2; le = e - EB2; E = E2C; nb = NB2; }
    int s = ei[le];
    int d = ei[E + le];
    const float2* xs = (const float2*)(x + (size_t)s * 6);
    float2* a = (float2*)(agg6 + (size_t)(nb + d) * 6);
    float2 v0 = xs[0], v1 = xs[1], v2 = xs[2];
    atomicAdd(&a[0], v0);
    atomicAdd(&a[1], v1);
    atomicAdd(&a[2], v2);
}

// conv1, all levels: h1 = relu(agg6 @ Wrel + brel + x @ Wroot); 32 nodes/block
#define C1_B0 1563
#define C1_B1 1954    // 1563 + 391
__global__ void conv1_all(const float* __restrict__ x0, const float* __restrict__ x1,
                          const float* __restrict__ x2,
                          const float* __restrict__ agg6,
                          const float* __restrict__ Wrel, const float* __restrict__ brel,
                          const float* __restrict__ Wroot, float* __restrict__ h1) {
    __shared__ float sx[32 * 6];
    __shared__ float sa[32 * 6];
    int b = blockIdx.x;
    int lvl = (b >= C1_B0) + (b >= C1_B1);
    const float* x;
    int tb, nlv, nb;
    if (lvl == 0)      { x = x0; tb = 0;     nlv = N0; nb = 0;   }
    else if (lvl == 1) { x = x1; tb = C1_B0; nlv = N1; nb = NB1; }
    else               { x = x2; tb = C1_B1; nlv = N2; nb = NB2; }
    int base = (b - tb) * 32;
    int cnt = nlv - base; if (cnt > 32) cnt = 32;
    int t = threadIdx.x;
    for (int idx = t; idx < cnt * 6; idx += 128) {
        sx[idx] = x[(size_t)base * 6 + idx];
        sa[idx] = agg6[(size_t)(nb + base) * 6 + idx];
    }
    __syncthreads();
    const float* Wr = Wrel + lvl * 6 * 128;
    const float* Wo = Wroot + lvl * 6 * 128;
    float wrel[6], wroot[6];
#pragma unroll
    for (int k = 0; k < 6; k++) { wrel[k] = Wr[k * 128 + t]; wroot[k] = Wo[k * 128 + t]; }
    float bb = brel[lvl * 128 + t];
    for (int j = 0; j < cnt; j++) {
        float acc = bb;
#pragma unroll
        for (int k = 0; k < 6; k++)
            acc = fmaf(sa[j * 6 + k], wrel[k], fmaf(sx[j * 6 + k], wroot[k], acc));
        h1[(size_t)(nb + base + j) * 128 + t] = fmaxf(acc, 0.f);
    }
}

// stage 2 aggregation: agg[dst] += h1[src] (128 feats); 4 edges per warp
__global__ void scatter128_all(const float* __restrict__ h1,
                               const int* __restrict__ ei0, const int* __restrict__ ei1,
                               const int* __restrict__ ei2,
                               float* __restrict__ agg) {
    int w = (blockIdx.x * blockDim.x + threadIdx.x) >> 5;
    int lane = threadIdx.x & 31;
    int e0 = w * 4;
    if (e0 >= ETOT) return;
    int lvl = (e0 >= EB1) + (e0 >= EB2);
    const int* ei;
    int le, E, nb;
    if (lvl == 0)      { ei = ei0; le = e0;       E = E0C; nb = 0;   }
    else if (lvl == 1) { ei = ei1; le = e0 - EB1; E = E1C; nb = NB1; }
    else               { ei = ei2; le = e0 - EB2; E = E2C; nb = NB2; }
    int s[4], d[4];
#pragma unroll
    for (int i = 0; i < 4; i++) { s[i] = ei[le + i]; d[i] = ei[E + le + i]; }
    float4 v[4];
#pragma unroll
    for (int i = 0; i < 4; i++)
        v[i] = *(const float4*)(h1 + (size_t)(nb + s[i]) * 128 + lane * 4);
#pragma unroll
    for (int i = 0; i < 4; i++)
        atomicAdd((float4*)(agg + (size_t)(nb + d[i]) * 128 + lane * 4), v[i]);
}

// fused conv2 + lin, all levels; 128-node tiles, 512 threads.
// warp = (node_group ng = w>>1 covering 16 nodes, f-half fh = w&1 covering 64 feats).
// h2 = relu(agg @ W1 + b + h1 @ W2) kept in smem, then e = h2 @ Wlin + blin
#define CL_B0 391
#define CL_B1 489     // 391 + 98; +25 for level 2 -> 514 total
__global__ void __launch_bounds__(512) conv2lin_all(
    const float* __restrict__ agg, const float* __restrict__ h1,
    const float* __restrict__ w1t, const float* __restrict__ w2t,
    const float* __restrict__ c2b,
    const float* __restrict__ lint, const float* __restrict__ linb,
    float* __restrict__ e) {
    extern __shared__ float smem[];
    float* s1 = smem;           // [128][128] acts (agg), later h2
    float* s2 = smem + 16384;   // [128][128] acts (h1)
    int b = blockIdx.x;
    int lvl = (b >= CL_B0) + (b >= CL_B1);
    int tb, nlv, nb0;
    if (lvl == 0)      { tb = 0;     nlv = N0; nb0 = 0;   }
    else if (lvl == 1) { tb = CL_B0; nlv = N1; nb0 = NB1; }
    else               { tb = CL_B1; nlv = N2; nb0 = NB2; }
    int base = (b - tb) * 128;
    int cnt = nlv - base; if (cnt > 128) cnt = 128;
    size_t row0 = (size_t)(nb0 + base) * 128;
    int t = threadIdx.x;
    for (int idx = t * 4; idx < cnt * 128; idx += 2048) {
        *(float4*)(s1 + idx) = *(const float4*)(agg + row0 + idx);
        *(float4*)(s2 + idx) = *(const float4*)(h1 + row0 + idx);
    }
    __syncthreads();
    int lane = t & 31;
    int w = t >> 5;
    int ng = w >> 1, fh = w & 1;
    int nbk = ng * 16;
    int f = fh * 64 + lane * 2;          // conv2 feature pair (f, f+1)
    const float* W1 = w1t + lvl * 16384;
    const float* W2 = w2t + lvl * 16384;
    float2 bias = *(const float2*)(c2b + lvl * 128 + f);
    ull acc[16][2];
#pragma unroll
    for (int j = 0; j < 16; j++) {
        acc[j][0] = pk2(bias.x, 0.f);
        acc[j][1] = pk2(bias.y, 0.f);
    }
#pragma unroll 2
    for (int m = 0; m < 64; m++) {
        ulonglong2 w1 = *(const ulonglong2*)(W1 + m * 256 + f * 2);
        ulonglong2 w2 = *(const ulonglong2*)(W2 + m * 256 + f * 2);
#pragma unroll
        for (int j = 0; j < 16; j++) {
            ull a1 = *(const ull*)(s1 + (nbk + j) * 128 + 2 * m);
            ull a2 = *(const ull*)(s2 + (nbk + j) * 128 + 2 * m);
            acc[j][0] = fma2(a1, w1.x, acc[j][0]);
            acc[j][1] = fma2(a1, w1.y, acc[j][1]);
            acc[j][0] = fma2(a2, w2.x, acc[j][0]);
            acc[j][1] = fma2(a2, w2.y, acc[j][1]);
        }
    }
    __syncthreads();   // all reads of s1 acts done before overwrite
    // h2 = relu(lo+hi) into s1
#pragma unroll
    for (int j = 0; j < 16; j++) {
        float2 r;
        r.x = fmaxf(hsum2(acc[j][0]), 0.f);
        r.y = fmaxf(hsum2(acc[j][1]), 0.f);
        *(float2*)(s1 + (nbk + j) * 128 + f) = r;
    }
    __syncthreads();
    // lin epilogue: e = h2 @ Wlin(128x96) + blin
    // fh=0: f_l = lane*2 (all lanes, f 0..62); fh=1: f_l = 64+lane*2, lanes 0..15
    int fl = fh * 64 + lane * 2;
    bool act = (fl < 96);
    if (act) {
        const float* WL = lint + lvl * 12288;
        float2 lb = *(const float2*)(linb + lvl * 96 + fl);
        ull acc2[16][2];
#pragma unroll
        for (int j = 0; j < 16; j++) {
            acc2[j][0] = pk2(lb.x, 0.f);
            acc2[j][1] = pk2(lb.y, 0.f);
        }
#pragma unroll 2
        for (int m = 0; m < 64; m++) {
            ulonglong2 wl = *(const ulonglong2*)(WL + m * 192 + fl * 2);
#pragma unroll
            for (int j = 0; j < 16; j++) {
                ull a = *(const ull*)(s1 + (nbk + j) * 128 + 2 * m);
                acc2[j][0] = fma2(a, wl.x, acc2[j][0]);
                acc2[j][1] = fma2(a, wl.y, acc2[j][1]);
            }
        }
#pragma unroll
        for (int j = 0; j < 16; j++) {
            if (nbk + j < cnt) {
                float2 r = make_float2(hsum2(acc2[j][0]), hsum2(acc2[j][1]));
                *(float2*)(e + (size_t)(nb0 + base + nbk + j) * 96 + fl) = r;
            }
        }
    }
}

// both interpolations fused; 4 nnz per warp, lanes 0..23
__global__ void interp_both(const float* __restrict__ e,
                            const int* __restrict__ A1r, const int* __restrict__ A1c,
                            const float* __restrict__ A1v,
                            const int* __restrict__ A2r, const int* __restrict__ A2c,
                            const float* __restrict__ A2v,
                            float* __restrict__ i1, float* __restrict__ i2) {
    int w = (blockIdx.x * blockDim.x + threadIdx.x) >> 5;
    int lane = threadIdx.x & 31;
    int q0 = w * 4;
    if (q0 >= 2 * NNZC) return;
    const int* Ar; const int* Ac; const float* Av; const float* ebase; float* dst; int off;
    if (q0 < NNZC) { Ar = A1r; Ac = A1c; Av = A1v;
                     ebase = e + (size_t)NB1 * 96; dst = i1; off = q0; }
    else           { Ar = A2r; Ac = A2c; Av = A2v;
                     ebase = e + (size_t)NB2 * 96; dst = i2; off = q0 - NNZC; }
    int r[4], c[4]; float v[4];
#pragma unroll
    for (int i = 0; i < 4; i++) { r[i] = Ar[off + i]; c[i] = Ac[off + i]; v[i] = Av[off + i]; }
    if (lane < 24) {
        float4 x[4];
#pragma unroll
        for (int i = 0; i < 4; i++)
            x[i] = *(const float4*)(ebase + (size_t)c[i] * 96 + lane * 4);
#pragma unroll
        for (int i = 0; i < 4; i++) {
            float4 y = make_float4(x[i].x * v[i], x[i].y * v[i], x[i].z * v[i], x[i].w * v[i]);
            atomicAdd((float4*)(dst + (size_t)r[i] * 96 + lane * 4), y);
        }
    }
}

// decoder GEMM: 128-node tiles; k-pair f32x2 with pair-packed weights (zero packs)
__global__ void __launch_bounds__(256) dec_gemm_kernel(
    const float* __restrict__ e0, const float* __restrict__ i1,
    const float* __restrict__ i2,
    const float* __restrict__ dect, const float* __restrict__ b0,
    const float* __restrict__ Wout, const float* __restrict__ bout,
    float* __restrict__ out, int n) {
    extern __shared__ float sin_[]; // [128][96]
    int base = blockIdx.x * 128;
    int cnt = n - base; if (cnt > 128) cnt = 128;
    int t = threadIdx.x;
    int lane = t & 31;
    int nb = (t >> 5) * 16;
#pragma unroll
    for (int br = 0; br < 3; br++) {
        __syncthreads();
        for (int idx = t; idx < cnt * 24; idx += 256) {
            int node = idx / 24, q = idx % 24;
            const float* srcp =
                (q < 8)  ? (e0 + (size_t)(base + node) * 96 + br * 32 + q * 4) :
                (q < 16) ? (i1 + (size_t)(base + node) * 96 + br * 32 + (q - 8) * 4) :
                           (i2 + (size_t)(base + node) * 96 + br * 32 + (q - 16) * 4);
            *(float4*)(sin_ + node * 96 + q * 4) = *(const float4*)srcp;
        }
        __syncthreads();
        const float* W = dect + br * 6144;
        float2 bb = *(const float2*)(b0 + br * 64 + 2 * lane);
        ull acc0[16], acc1[16];
        ull b0p = pk2(bb.x, 0.f), b1p = pk2(bb.y, 0.f);
#pragma unroll
        for (int j = 0; j < 16; j++) { acc0[j] = b0p; acc1[j] = b1p; }
        for (int m = 0; m < 48; m++) {
            ulonglong2 w = *(const ulonglong2*)(W + m * 128 + lane * 4);
#pragma unroll
            for (int j = 0; j < 16; j++) {
                ull a = *(const ull*)(sin_ + (nb + j) * 96 + 2 * m);
                acc0[j] = fma2(a, w.x, acc0[j]);
                acc1[j] = fma2(a, w.y, acc1[j]);
            }
        }
        float2 wo = *(const float2*)(Wout + br * 64 + 2 * lane);
        float bo = bout[br];
#pragma unroll
        for (int j = 0; j < 16; j++) {
            float h0 = hsum2(acc0[j]);
            float h1 = hsum2(acc1[j]);
            h0 = h0 > 0.f ? h0 : expm1f(h0);
            h1 = h1 > 0.f ? h1 : expm1f(h1);
            float r = fmaf(h0, wo.x, h1 * wo.y);
#pragma unroll
            for (int s = 16; s > 0; s >>= 1)
                r += __shfl_xor_sync(0xffffffffu, r, s);
            if (lane == 0 && nb + j < cnt)
                out[(size_t)(base + nb + j) * 3 + br] = r + bo;
        }
    }
}

// ---------------- host orchestration: 7 launches ----------------

extern "C" void kernel_launch(void* const* d_in, const int* in_sizes, int n_in,
                              void* d_out, int out_size) {
    const float* x0 = (const float*)d_in[0];
    const float* x1 = (const float*)d_in[1];
    const float* x2 = (const float*)d_in[2];
    const int* ei0 = (const int*)d_in[3];
    const int* ei1 = (const int*)d_in[4];
    const int* ei2 = (const int*)d_in[5];
    const int*   A1r = (const int*)d_in[6];
    const int*   A1c = (const int*)d_in[7];
    const float* A1v = (const float*)d_in[8];
    const int*   A2r = (const int*)d_in[9];
    const int*   A2c = (const int*)d_in[10];
    const float* A2v = (const float*)d_in[11];
    const float* c1Wrel  = (const float*)d_in[12];
    const float* c1brel  = (const float*)d_in[13];
    const float* c1Wroot = (const float*)d_in[14];
    const float* c2Wrel  = (const float*)d_in[15];
    const float* c2brel  = (const float*)d_in[16];
    const float* c2Wroot = (const float*)d_in[17];
    const float* linW = (const float*)d_in[18];
    const float* linb = (const float*)d_in[19];
    const float* dW0   = (const float*)d_in[20];
    const float* db0   = (const float*)d_in[21];
    const float* dWout = (const float*)d_in[22];
    const float* dbout = (const float*)d_in[23];
    float* out = (float*)d_out;

    void* p;
    cudaGetSymbolAddress(&p, g_zr);   float* zr   = (float*)p;
    cudaGetSymbolAddress(&p, g_h1);   float* h1   = (float*)p;
    cudaGetSymbolAddress(&p, g_e);    float* e    = (float*)p;
    cudaGetSymbolAddress(&p, g_w1t);  float* w1t  = (float*)p;
    cudaGetSymbolAddress(&p, g_w2t);  float* w2t  = (float*)p;
    cudaGetSymbolAddress(&p, g_lint); float* lint = (float*)p;
    cudaGetSymbolAddress(&p, g_dect); float* dect = (float*)p;
    float* agg6 = zr + AGG6_OFF;
    float* agg  = zr + AGG_OFF;
    float* i1b  = zr + I1_OFF;
    float* i2b  = zr + I2_OFF;

    cudaFuncSetAttribute(conv2lin_all, cudaFuncAttributeMaxDynamicSharedMemorySize, 131072);
    cudaFuncSetAttribute(dec_gemm_kernel, cudaFuncAttributeMaxDynamicSharedMemorySize, 49152);

    prep_kernel<<<cdiv(ZR_TOT / 4, 256), 256>>>(c2Wrel, c2Wroot, linW, dW0,
                                                w1t, w2t, lint, dect,
                                                (float4*)zr, ZR_TOT / 4);
    scatter6_all<<<cdiv(ETOT, 256), 256>>>(x0, x1, x2, ei0, ei1, ei2, agg6);
    conv1_all<<<C1_B1 + 98, 128>>>(x0, x1, x2, agg6, c1Wrel, c1brel, c1Wroot, h1);
    scatter128_all<<<cdiv((ETOT / 4) * 32, 256), 256>>>(h1, ei0, ei1, ei2, agg);
    conv2lin_all<<<CL_B1 + 25, 512, 131072>>>(agg, h1, w1t, w2t, c2brel,
                                              lint, linb, e);
    interp_both<<<cdiv((2 * NNZC / 4) * 32, 256), 256>>>(e, A1r, A1c, A1v,
                                                         A2r, A2c, A2v, i1b, i2b);
    dec_gemm_kernel<<<cdiv(N0, 128), 256, 49152>>>(e, i1b, i2b, dect, db0,
                                                   dWout, dbout, out, N0);
}

// round 7
// speedup vs baseline: 1.1051x; 1.1051x over previous
#include <cuda_runtime.h>
#include <math.h>

#define N0 50000
#define N1 12500
#define N2 3125
#define NTOT 65625            // N0+N1+N2
#define E0C 800000
#define E1C 200000
#define E2C 50000
#define ETOT 1050000
#define NNZC 200000

// node row offsets per level
#define NB1 50000
#define NB2 62500
// edge offsets
#define EB1 800000
#define EB2 1000000

// -------- fused zeroed scratch region: [agg6 | agg | i1 | i2] --------
#define AGG6_OFF 0
#define AGG_OFF  393752
#define I1_OFF   8793752
#define I2_OFF   13593752
#define ZR_TOT   18393752

__device__ float g_zr[ZR_TOT];
__device__ float g_h1[NTOT * 128];
__device__ float g_e [NTOT * 96];
// pair-interleaved (along k) weight copies
__device__ float g_w1t[3 * 16384];
__device__ float g_w2t[3 * 16384];
__device__ float g_lint[3 * 12288];
__device__ float g_dect[3 * 6144];

static inline int cdiv(int a, int b) { return (a + b - 1) / b; }

// ---------------- f32x2 helpers ----------------
typedef unsigned long long ull;
__device__ __forceinline__ ull pk2(float x, float y) {
    ull r; asm("mov.b64 %0, {%1, %2};" : "=l"(r) : "f"(x), "f"(y)); return r;
}
__device__ __forceinline__ ull fma2(ull a, ull b, ull c) {
    ull d; asm("fma.rn.f32x2 %0, %1, %2, %3;" : "=l"(d) : "l"(a), "l"(b), "l"(c));
    return d;
}
__device__ __forceinline__ float2 up2(ull v) {
    float2 f; asm("mov.b64 {%0, %1}, %2;" : "=f"(f.x), "=f"(f.y) : "l"(v)); return f;
}
__device__ __forceinline__ float hsum2(ull v) { float2 f = up2(v); return f.x + f.y; }

// ---------------- prep: weight repack + scratch zero in one launch ----------------
// repack: Wt[m][f][2] = (W[2m][f], W[2m+1][f])
__global__ void prep_kernel(const float* __restrict__ W1, const float* __restrict__ W2,
                            const float* __restrict__ linW, const float* __restrict__ decW,
                            float* __restrict__ w1t, float* __restrict__ w2t,
                            float* __restrict__ lint, float* __restrict__ dect,
                            float4* __restrict__ zr, int nq) {
    int i = blockIdx.x * blockDim.x + threadIdx.x;
    if (i < nq) zr[i] = make_float4(0.f, 0.f, 0.f, 0.f);
    if (i < 24576) {                       // 3 lvl x 64 m x 128 f
        int lvl = i / 8192, r = i % 8192, m = r / 128, f = r % 128;
        int src = lvl * 16384, dst = lvl * 16384 + m * 256 + f * 2;
        w1t[dst]     = W1[src + (2 * m) * 128 + f];
        w1t[dst + 1] = W1[src + (2 * m + 1) * 128 + f];
        w2t[dst]     = W2[src + (2 * m) * 128 + f];
        w2t[dst + 1] = W2[src + (2 * m + 1) * 128 + f];
    } else if (i < 24576 + 18432) {        // 3 lvl x 64 m x 96 f
        int q = i - 24576;
        int lvl = q / 6144, r = q % 6144, m = r / 96, f = r % 96;
        lint[lvl * 12288 + m * 192 + f * 2]     = linW[lvl * 12288 + (2 * m) * 96 + f];
        lint[lvl * 12288 + m * 192 + f * 2 + 1] = linW[lvl * 12288 + (2 * m + 1) * 96 + f];
    } else if (i < 24576 + 18432 + 9216) { // 3 br x 48 m x 64 h
        int q = i - 43008;
        int br = q / 3072, r = q % 3072, m = r / 64, h = r % 64;
        dect[br * 6144 + m * 128 + h * 2]     = decW[br * 6144 + (2 * m) * 64 + h];
        dect[br * 6144 + m * 128 + h * 2 + 1] = decW[br * 6144 + (2 * m + 1) * 64 + h];
    }
}

// ---------------- kernels ----------------

// stage 1 aggregation: agg6[dst] += x[src] (6 feats), float2 RED
__global__ void scatter6_all(const float* __restrict__ x0, const float* __restrict__ x1,
                             const float* __restrict__ x2,
                             const int* __restrict__ ei0, const int* __restrict__ ei1,
                             const int* __restrict__ ei2,
                             float* __restrict__ agg6) {
    int e = blockIdx.x * blockDim.x + threadIdx.x;
    if (e >= ETOT) return;
    int lvl = (e >= EB1) + (e >= EB2);
    const int* ei;
    const float* x;
    int le, E, nb;
    if (lvl == 0)      { ei = ei0; x = x0; le = e;       E = E0C; nb = 0;   }
    else if (lvl == 1) { ei = ei1; x = x1; le = e - EB1; E = E1C; nb = NB1; }
    else               { ei = ei2; x = x2; le = e - EB2; E = E2C; nb = NB2; }
    int s = ei[le];
    int d = ei[E + le];
    const float2* xs = (const float2*)(x + (size_t)s * 6);
    float2* a = (float2*)(agg6 + (size_t)(nb + d) * 6);
    float2 v0 = xs[0], v1 = xs[1], v2 = xs[2];
    atomicAdd(&a[0], v0);
    atomicAdd(&a[1], v1);
    atomicAdd(&a[2], v2);
}

// conv1, all levels: h1 = relu(agg6 @ Wrel + brel + x @ Wroot); 32 nodes/block
#define C1_B0 1563
#define C1_B1 1954    // 1563 + 391
__global__ void conv1_all(const float* __restrict__ x0, const float* __restrict__ x1,
                          const float* __restrict__ x2,
                          const float* __restrict__ agg6,
                          const float* __restrict__ Wrel, const float* __restrict__ brel,
                          const float* __restrict__ Wroot, float* __restrict__ h1) {
    __shared__ float sx[32 * 6];
    __shared__ float sa[32 * 6];
    int b = blockIdx.x;
    int lvl = (b >= C1_B0) + (b >= C1_B1);
    const float* x;
    int tb, nlv, nb;
    if (lvl == 0)      { x = x0; tb = 0;     nlv = N0; nb = 0;   }
    else if (lvl == 1) { x = x1; tb = C1_B0; nlv = N1; nb = NB1; }
    else               { x = x2; tb = C1_B1; nlv = N2; nb = NB2; }
    int base = (b - tb) * 32;
    int cnt = nlv - base; if (cnt > 32) cnt = 32;
    int t = threadIdx.x;
    for (int idx = t; idx < cnt * 6; idx += 128) {
        sx[idx] = x[(size_t)base * 6 + idx];
        sa[idx] = agg6[(size_t)(nb + base) * 6 + idx];
    }
    __syncthreads();
    const float* Wr = Wrel + lvl * 6 * 128;
    const float* Wo = Wroot + lvl * 6 * 128;
    float wrel[6], wroot[6];
#pragma unroll
    for (int k = 0; k < 6; k++) { wrel[k] = Wr[k * 128 + t]; wroot[k] = Wo[k * 128 + t]; }
    float bb = brel[lvl * 128 + t];
    for (int j = 0; j < cnt; j++) {
        float acc = bb;
#pragma unroll
        for (int k = 0; k < 6; k++)
            acc = fmaf(sa[j * 6 + k], wrel[k], fmaf(sx[j * 6 + k], wroot[k], acc));
        h1[(size_t)(nb + base + j) * 128 + t] = fmaxf(acc, 0.f);
    }
}

// stage 2 aggregation: agg[dst] += h1[src] (128 feats); 4 edges per warp
__global__ void scatter128_all(const float* __restrict__ h1,
                               const int* __restrict__ ei0, const int* __restrict__ ei1,
                               const int* __restrict__ ei2,
                               float* __restrict__ agg) {
    int w = (blockIdx.x * blockDim.x + threadIdx.x) >> 5;
    int lane = threadIdx.x & 31;
    int e0 = w * 4;
    if (e0 >= ETOT) return;
    int lvl = (e0 >= EB1) + (e0 >= EB2);
    const int* ei;
    int le, E, nb;
    if (lvl == 0)      { ei = ei0; le = e0;       E = E0C; nb = 0;   }
    else if (lvl == 1) { ei = ei1; le = e0 - EB1; E = E1C; nb = NB1; }
    else               { ei = ei2; le = e0 - EB2; E = E2C; nb = NB2; }
    int s[4], d[4];
#pragma unroll
    for (int i = 0; i < 4; i++) { s[i] = ei[le + i]; d[i] = ei[E + le + i]; }
    float4 v[4];
#pragma unroll
    for (int i = 0; i < 4; i++)
        v[i] = *(const float4*)(h1 + (size_t)(nb + s[i]) * 128 + lane * 4);
#pragma unroll
    for (int i = 0; i < 4; i++)
        atomicAdd((float4*)(agg + (size_t)(nb + d[i]) * 128 + lane * 4), v[i]);
}

// fused conv2 + lin, all levels; 64-node tiles (round-5 shape), m-unroll x2,
// 16B broadcast activation loads. h2 kept in smem, then lin epilogue.
#define CL_B0 782
#define CL_B1 978     // 782 + 196; +49 for level 2 -> 1027 total
__global__ void __launch_bounds__(256, 2) conv2lin_all(
    const float* __restrict__ agg, const float* __restrict__ h1,
    const float* __restrict__ w1t, const float* __restrict__ w2t,
    const float* __restrict__ c2b,
    const float* __restrict__ lint, const float* __restrict__ linb,
    float* __restrict__ e) {
    extern __shared__ float smem[];
    float* s1 = smem;           // [64][128]
    float* s2 = smem + 8192;    // [64][128]
    int b = blockIdx.x;
    int lvl = (b >= CL_B0) + (b >= CL_B1);
    int tb, nlv, nb0;
    if (lvl == 0)      { tb = 0;     nlv = N0; nb0 = 0;   }
    else if (lvl == 1) { tb = CL_B0; nlv = N1; nb0 = NB1; }
    else               { tb = CL_B1; nlv = N2; nb0 = NB2; }
    int base = (b - tb) * 64;
    int cnt = nlv - base; if (cnt > 64) cnt = 64;
    size_t row0 = (size_t)(nb0 + base) * 128;
    int t = threadIdx.x;
    for (int idx = t * 4; idx < cnt * 128; idx += 1024) {
        *(float4*)(s1 + idx) = *(const float4*)(agg + row0 + idx);
        *(float4*)(s2 + idx) = *(const float4*)(h1 + row0 + idx);
    }
    __syncthreads();
    int lane = t & 31;
    int f = lane * 4;
    int nbk = (t >> 5) * 8;
    const float* W1 = w1t + lvl * 16384;
    const float* W2 = w2t + lvl * 16384;
    float4 bias = *(const float4*)(c2b + lvl * 128 + f);
    ull acc[8][4];
#pragma unroll
    for (int j = 0; j < 8; j++) {
        acc[j][0] = pk2(bias.x, 0.f);
        acc[j][1] = pk2(bias.y, 0.f);
        acc[j][2] = pk2(bias.z, 0.f);
        acc[j][3] = pk2(bias.w, 0.f);
    }
    for (int m = 0; m < 64; m += 2) {
        // weights for k-pairs m and m+1 (8 x LDG.128)
        ulonglong2 w1a = *(const ulonglong2*)(W1 + m * 256 + f * 2);
        ulonglong2 w1b = *(const ulonglong2*)(W1 + m * 256 + f * 2 + 4);
        ulonglong2 w1c = *(const ulonglong2*)(W1 + (m + 1) * 256 + f * 2);
        ulonglong2 w1d = *(const ulonglong2*)(W1 + (m + 1) * 256 + f * 2 + 4);
        ulonglong2 w2a = *(const ulonglong2*)(W2 + m * 256 + f * 2);
        ulonglong2 w2b = *(const ulonglong2*)(W2 + m * 256 + f * 2 + 4);
        ulonglong2 w2c = *(const ulonglong2*)(W2 + (m + 1) * 256 + f * 2);
        ulonglong2 w2d = *(const ulonglong2*)(W2 + (m + 1) * 256 + f * 2 + 4);
#pragma unroll
        for (int j = 0; j < 8; j++) {
            // 16B broadcast loads: 4 consecutive k-values (2 pairs)
            ulonglong2 a1 = *(const ulonglong2*)(s1 + (nbk + j) * 128 + 2 * m);
            ulonglong2 a2 = *(const ulonglong2*)(s2 + (nbk + j) * 128 + 2 * m);
            acc[j][0] = fma2(a1.x, w1a.x, acc[j][0]);
            acc[j][1] = fma2(a1.x, w1a.y, acc[j][1]);
            acc[j][2] = fma2(a1.x, w1b.x, acc[j][2]);
            acc[j][3] = fma2(a1.x, w1b.y, acc[j][3]);
            acc[j][0] = fma2(a1.y, w1c.x, acc[j][0]);
            acc[j][1] = fma2(a1.y, w1c.y, acc[j][1]);
            acc[j][2] = fma2(a1.y, w1d.x, acc[j][2]);
            acc[j][3] = fma2(a1.y, w1d.y, acc[j][3]);
            acc[j][0] = fma2(a2.x, w2a.x, acc[j][0]);
            acc[j][1] = fma2(a2.x, w2a.y, acc[j][1]);
            acc[j][2] = fma2(a2.x, w2b.x, acc[j][2]);
            acc[j][3] = fma2(a2.x, w2b.y, acc[j][3]);
            acc[j][0] = fma2(a2.y, w2c.x, acc[j][0]);
            acc[j][1] = fma2(a2.y, w2c.y, acc[j][1]);
            acc[j][2] = fma2(a2.y, w2d.x, acc[j][2]);
            acc[j][3] = fma2(a2.y, w2d.y, acc[j][3]);
        }
    }
    // h2 = relu(lo+hi) back into s1 (warp-local rows)
#pragma unroll
    for (int j = 0; j < 8; j++) {
        float4 r;
        r.x = fmaxf(hsum2(acc[j][0]), 0.f);
        r.y = fmaxf(hsum2(acc[j][1]), 0.f);
        r.z = fmaxf(hsum2(acc[j][2]), 0.f);
        r.w = fmaxf(hsum2(acc[j][3]), 0.f);
        *(float4*)(s1 + (nbk + j) * 128 + f) = r;
    }
    __syncwarp();
    // lin epilogue: e = h2 @ Wlin(128x96) + blin; lanes 0..23 active
    if (f < 96) {
        const float* WL = lint + lvl * 12288;
        float4 lb = *(const float4*)(linb + lvl * 96 + f);
        ull acc2[8][4];
#pragma unroll
        for (int j = 0; j < 8; j++) {
            acc2[j][0] = pk2(lb.x, 0.f);
            acc2[j][1] = pk2(lb.y, 0.f);
            acc2[j][2] = pk2(lb.z, 0.f);
            acc2[j][3] = pk2(lb.w, 0.f);
        }
        for (int m = 0; m < 64; m += 2) {
            ulonglong2 wa = *(const ulonglong2*)(WL + m * 192 + f * 2);
            ulonglong2 wb = *(const ulonglong2*)(WL + m * 192 + f * 2 + 4);
            ulonglong2 wc = *(const ulonglong2*)(WL + (m + 1) * 192 + f * 2);
            ulonglong2 wd = *(const ulonglong2*)(WL + (m + 1) * 192 + f * 2 + 4);
#pragma unroll
            for (int j = 0; j < 8; j++) {
                ulonglong2 a = *(const ulonglong2*)(s1 + (nbk + j) * 128 + 2 * m);
                acc2[j][0] = fma2(a.x, wa.x, acc2[j][0]);
                acc2[j][1] = fma2(a.x, wa.y, acc2[j][1]);
                acc2[j][2] = fma2(a.x, wb.x, acc2[j][2]);
                acc2[j][3] = fma2(a.x, wb.y, acc2[j][3]);
                acc2[j][0] = fma2(a.y, wc.x, acc2[j][0]);
                acc2[j][1] = fma2(a.y, wc.y, acc2[j][1]);
                acc2[j][2] = fma2(a.y, wd.x, acc2[j][2]);
                acc2[j][3] = fma2(a.y, wd.y, acc2[j][3]);
            }
        }
#pragma unroll
        for (int j = 0; j < 8; j++) {
            if (nbk + j < cnt) {
                float4 r = make_float4(hsum2(acc2[j][0]), hsum2(acc2[j][1]),
                                       hsum2(acc2[j][2]), hsum2(acc2[j][3]));
                *(float4*)(e + (size_t)(nb0 + base + nbk + j) * 96 + f) = r;
            }
        }
    }
}

// both interpolations fused; 4 nnz per warp, lanes 0..23
__global__ void interp_both(const float* __restrict__ e,
                            const int* __restrict__ A1r, const int* __restrict__ A1c,
                            const float* __restrict__ A1v,
                            const int* __restrict__ A2r, const int* __restrict__ A2c,
                            const float* __restrict__ A2v,
                            float* __restrict__ i1, float* __restrict__ i2) {
    int w = (blockIdx.x * blockDim.x + threadIdx.x) >> 5;
    int lane = threadIdx.x & 31;
    int q0 = w * 4;
    if (q0 >= 2 * NNZC) return;
    const int* Ar; const int* Ac; const float* Av; const float* ebase; float* dst; int off;
    if (q0 < NNZC) { Ar = A1r; Ac = A1c; Av = A1v;
                     ebase = e + (size_t)NB1 * 96; dst = i1; off = q0; }
    else           { Ar = A2r; Ac = A2c; Av = A2v;
                     ebase = e + (size_t)NB2 * 96; dst = i2; off = q0 - NNZC; }
    int r[4], c[4]; float v[4];
#pragma unroll
    for (int i = 0; i < 4; i++) { r[i] = Ar[off + i]; c[i] = Ac[off + i]; v[i] = Av[off + i]; }
    if (lane < 24) {
        float4 x[4];
#pragma unroll
        for (int i = 0; i < 4; i++)
            x[i] = *(const float4*)(ebase + (size_t)c[i] * 96 + lane * 4);
#pragma unroll
        for (int i = 0; i < 4; i++) {
            float4 y = make_float4(x[i].x * v[i], x[i].y * v[i], x[i].z * v[i], x[i].w * v[i]);
            atomicAdd((float4*)(dst + (size_t)r[i] * 96 + lane * 4), y);
        }
    }
}

// decoder GEMM: 128-node tiles; k-pair f32x2 pair-packed weights, m-unroll x2
__global__ void __launch_bounds__(256) dec_gemm_kernel(
    const float* __restrict__ e0, const float* __restrict__ i1,
    const float* __restrict__ i2,
    const float* __restrict__ dect, const float* __restrict__ b0,
    const float* __restrict__ Wout, const float* __restrict__ bout,
    float* __restrict__ out, int n) {
    extern __shared__ float sin_[]; // [128][96]
    int base = blockIdx.x * 128;
    int cnt = n - base; if (cnt > 128) cnt = 128;
    int t = threadIdx.x;
    int lane = t & 31;
    int nb = (t >> 5) * 16;
#pragma unroll
    for (int br = 0; br < 3; br++) {
        __syncthreads();
        for (int idx = t; idx < cnt * 24; idx += 256) {
            int node = idx / 24, q = idx % 24;
            const float* srcp =
                (q < 8)  ? (e0 + (size_t)(base + node) * 96 + br * 32 + q * 4) :
                (q < 16) ? (i1 + (size_t)(base + node) * 96 + br * 32 + (q - 8) * 4) :
                           (i2 + (size_t)(base + node) * 96 + br * 32 + (q - 16) * 4);
            *(float4*)(sin_ + node * 96 + q * 4) = *(const float4*)srcp;
        }
        __syncthreads();
        const float* W = dect + br * 6144;
        float2 bb = *(const float2*)(b0 + br * 64 + 2 * lane);
        ull acc0[16], acc1[16];
        ull b0p = pk2(bb.x, 0.f), b1p = pk2(bb.y, 0.f);
#pragma unroll
        for (int j = 0; j < 16; j++) { acc0[j] = b0p; acc1[j] = b1p; }
        for (int m = 0; m < 48; m += 2) {
            ulonglong2 wA = *(const ulonglong2*)(W + m * 128 + lane * 4);
            ulonglong2 wB = *(const ulonglong2*)(W + (m + 1) * 128 + lane * 4);
#pragma unroll
            for (int j = 0; j < 16; j++) {
                ulonglong2 a = *(const ulonglong2*)(sin_ + (nb + j) * 96 + 2 * m);
                acc0[j] = fma2(a.x, wA.x, acc0[j]);
                acc1[j] = fma2(a.x, wA.y, acc1[j]);
                acc0[j] = fma2(a.y, wB.x, acc0[j]);
                acc1[j] = fma2(a.y, wB.y, acc1[j]);
            }
        }
        float2 wo = *(const float2*)(Wout + br * 64 + 2 * lane);
        float bo = bout[br];
#pragma unroll
        for (int j = 0; j < 16; j++) {
            float h0 = hsum2(acc0[j]);
            float h1 = hsum2(acc1[j]);
            h0 = h0 > 0.f ? h0 : expm1f(h0);
            h1 = h1 > 0.f ? h1 : expm1f(h1);
            float r = fmaf(h0, wo.x, h1 * wo.y);
#pragma unroll
            for (int s = 16; s > 0; s >>= 1)
                r += __shfl_xor_sync(0xffffffffu, r, s);
            if (lane == 0 && nb + j < cnt)
                out[(size_t)(base + nb + j) * 3 + br] = r + bo;
        }
    }
}

// ---------------- host orchestration: 7 launches ----------------

extern "C" void kernel_launch(void* const* d_in, const int* in_sizes, int n_in,
                              void* d_out, int out_size) {
    const float* x0 = (const float*)d_in[0];
    const float* x1 = (const float*)d_in[1];
    const float* x2 = (const float*)d_in[2];
    const int* ei0 = (const int*)d_in[3];
    const int* ei1 = (const int*)d_in[4];
    const int* ei2 = (const int*)d_in[5];
    const int*   A1r = (const int*)d_in[6];
    const int*   A1c = (const int*)d_in[7];
    const float* A1v = (const float*)d_in[8];
    const int*   A2r = (const int*)d_in[9];
    const int*   A2c = (const int*)d_in[10];
    const float* A2v = (const float*)d_in[11];
    const float* c1Wrel  = (const float*)d_in[12];
    const float* c1brel  = (const float*)d_in[13];
    const float* c1Wroot = (const float*)d_in[14];
    const float* c2Wrel  = (const float*)d_in[15];
    const float* c2brel  = (const float*)d_in[16];
    const float* c2Wroot = (const float*)d_in[17];
    const float* linW = (const float*)d_in[18];
    const float* linb = (const float*)d_in[19];
    const float* dW0   = (const float*)d_in[20];
    const float* db0   = (const float*)d_in[21];
    const float* dWout = (const float*)d_in[22];
    const float* dbout = (const float*)d_in[23];
    float* out = (float*)d_out;

    void* p;
    cudaGetSymbolAddress(&p, g_zr);   float* zr   = (float*)p;
    cudaGetSymbolAddress(&p, g_h1);   float* h1   = (float*)p;
    cudaGetSymbolAddress(&p, g_e);    float* e    = (float*)p;
    cudaGetSymbolAddress(&p, g_w1t);  float* w1t  = (float*)p;
    cudaGetSymbolAddress(&p, g_w2t);  float* w2t  = (float*)p;
    cudaGetSymbolAddress(&p, g_lint); float* lint = (float*)p;
    cudaGetSymbolAddress(&p, g_dect); float* dect = (float*)p;
    float* agg6 = zr + AGG6_OFF;
    float* agg  = zr + AGG_OFF;
    float* i1b  = zr + I1_OFF;
    float* i2b  = zr + I2_OFF;

    cudaFuncSetAttribute(conv2lin_all, cudaFuncAttributeMaxDynamicSharedMemorySize, 65536);
    cudaFuncSetAttribute(dec_gemm_kernel, cudaFuncAttributeMaxDynamicSharedMemorySize, 49152);

    prep_kernel<<<cdiv(ZR_TOT / 4, 256), 256>>>(c2Wrel, c2Wroot, linW, dW0,
                                                w1t, w2t, lint, dect,
                                                (float4*)zr, ZR_TOT / 4);
    scatter6_all<<<cdiv(ETOT, 256), 256>>>(x0, x1, x2, ei0, ei1, ei2, agg6);
    conv1_all<<<C1_B1 + 98, 128>>>(x0, x1, x2, agg6, c1Wrel, c1brel, c1Wroot, h1);
    scatter128_all<<<cdiv((ETOT / 4) * 32, 256), 256>>>(h1, ei0, ei1, ei2, agg);
    conv2lin_all<<<CL_B1 + 49, 256, 65536>>>(agg, h1, w1t, w2t, c2brel,
                                             lint, linb, e);
    interp_both<<<cdiv((2 * NNZC / 4) * 32, 256), 256>>>(e, A1r, A1c, A1v,
                                                         A2r, A2c, A2v, i1b, i2b);
    dec_gemm_kernel<<<cdiv(N0, 128), 256, 49152>>>(e, i1b, i2b, dect, db0,
                                                   dWout, dbout, out, N0);
}

// round 9
// speedup vs baseline: 1.2420x; 1.1239x over previous
#include <cuda_runtime.h>
#include <cuda_bf16.h>
#include <math.h>

#define N0 50000
#define N1 12500
#define N2 3125
#define NTOT 65625
#define E0C 800000
#define E1C 200000
#define E2C 50000
#define ETOT 1050000
#define NNZC 200000

#define NB1 50000
#define NB2 62500
#define EB1 800000
#define EB2 1000000

// -------- fused zeroed scratch region: [agg6 | agg | i1 | i2] --------
#define AGG6_OFF 0
#define AGG_OFF  393752
#define I1_OFF   8793752
#define I2_OFF   13593752
#define ZR_TOT   18393752

__device__ float g_zr[ZR_TOT];
__device__ __align__(16) float g_h1[NTOT * 128];
__device__ float g_e [NTOT * 96];
__device__ float g_dect[3 * 6144];
// per-level bf16 weight blob: [W1h|W1l|W2h|W2l] 4x(128x136) + [Lh|Ll] 2x(96x136)
#define WTILE 17408            // 128*136 bf16 elems
#define LTILE 13056            // 96*136
#define WB_LVL 95744           // 4*WTILE + 2*LTILE elems
__device__ __align__(16) __nv_bfloat16 g_wblob[3 * WB_LVL];

static inline int cdiv(int a, int b) { return (a + b - 1) / b; }

// ---------------- f32x2 helpers (dec path) ----------------
typedef unsigned long long ull;
__device__ __forceinline__ ull pk2(float x, float y) {
    ull r; asm("mov.b64 %0, {%1, %2};" : "=l"(r) : "f"(x), "f"(y)); return r;
}
__device__ __forceinline__ ull fma2(ull a, ull b, ull c) {
    ull d; asm("fma.rn.f32x2 %0, %1, %2, %3;" : "=l"(d) : "l"(a), "l"(b), "l"(c));
    return d;
}
__device__ __forceinline__ float2 up2(ull v) {
    float2 f; asm("mov.b64 {%0, %1}, %2;" : "=f"(f.x), "=f"(f.y) : "l"(v)); return f;
}
__device__ __forceinline__ float hsum2(ull v) { float2 f = up2(v); return f.x + f.y; }

// ---------------- bf16 helpers ----------------
__device__ __forceinline__ unsigned pack_bf16x2(float lo_f, float hi_f) {
    unsigned r;
    asm("cvt.rn.bf16x2.f32 %0, %1, %2;" : "=r"(r) : "f"(hi_f), "f"(lo_f));
    return r;
}
__device__ __forceinline__ float bf16rn(float x) {
    return __bfloat162float(__float2bfloat16(x));
}

// mma.sync m16n8k16 bf16 (baseline sm_80+ feature, compiles for compute_103)
__device__ __forceinline__ void mma_bf16(float c[4], const unsigned a[4],
                                         unsigned b0, unsigned b1) {
    asm volatile(
        "mma.sync.aligned.m16n8k16.row.col.f32.bf16.bf16.f32 "
        "{%0,%1,%2,%3}, {%4,%5,%6,%7}, {%8,%9}, {%0,%1,%2,%3};"
        : "+f"(c[0]), "+f"(c[1]), "+f"(c[2]), "+f"(c[3])
        : "r"(a[0]), "r"(a[1]), "r"(a[2]), "r"(a[3]), "r"(b0), "r"(b1));
}

// one K=128 GEMM section: acc[2][NT][4] += A(128x128 bf16, 136-stride) @ B^T(NTx8 rows)
template<int NT>
__device__ __forceinline__ void run_section(
    float (*acc)[NT][4],
    const __nv_bfloat16* __restrict__ At, const __nv_bfloat16* __restrict__ Wt,
    int wm, int wn_base, int lane) {
    int rbase = wm * 32 + (lane >> 2);
    int kc = (lane & 3) * 2;
#pragma unroll
    for (int ks = 0; ks < 8; ks++) {
        int k0 = ks * 16 + kc;
        unsigned a[2][4];
#pragma unroll
        for (int mt = 0; mt < 2; mt++) {
            const __nv_bfloat16* p = At + (rbase + mt * 16) * 136 + k0;
            a[mt][0] = *(const unsigned*)p;
            a[mt][1] = *(const unsigned*)(p + 8 * 136);
            a[mt][2] = *(const unsigned*)(p + 8);
            a[mt][3] = *(const unsigned*)(p + 8 * 136 + 8);
        }
#pragma unroll
        for (int nt = 0; nt < NT; nt++) {
            const __nv_bfloat16* q = Wt + (wn_base + nt * 8 + (lane >> 2)) * 136 + k0;
            unsigned b0 = *(const unsigned*)q;
            unsigned b1 = *(const unsigned*)(q + 8);
            mma_bf16(acc[0][nt], a[0], b0, b1);
            mma_bf16(acc[1][nt], a[1], b0, b1);
        }
    }
}

// ---------------- prep: zero + bf16 split-transpose weights + dec repack ----------------
__global__ void prep_kernel(const float* __restrict__ W1, const float* __restrict__ W2,
                            const float* __restrict__ linW, const float* __restrict__ decW,
                            __nv_bfloat16* __restrict__ wblob, float* __restrict__ dect,
                            float4* __restrict__ zr, int nq) {
    int i = blockIdx.x * blockDim.x + threadIdx.x;
    if (i < nq) zr[i] = make_float4(0.f, 0.f, 0.f, 0.f);
    if (i < 98304) {                        // conv2: 3 lvl x 2 chunk x 128k x 128f
        int lvl = i / 32768, r = i % 32768;
        int chunk = r / 16384, q = r % 16384;
        int k = q / 128, f = q % 128;
        float w = (chunk == 0 ? W1 : W2)[lvl * 16384 + k * 128 + f];
        float hi = bf16rn(w);
        __nv_bfloat16* base = wblob + lvl * WB_LVL + chunk * 2 * WTILE;
        base[f * 136 + k]         = __float2bfloat16(hi);
        base[WTILE + f * 136 + k] = __float2bfloat16(w - hi);
    } else if (i < 98304 + 36864) {         // lin: 3 lvl x 128k x 96f
        int q = i - 98304;
        int lvl = q / 12288, r = q % 12288;
        int k = r / 96, f = r % 96;
        float w = linW[lvl * 12288 + k * 96 + f];
        float hi = bf16rn(w);
        __nv_bfloat16* base = wblob + lvl * WB_LVL + 4 * WTILE;
        base[f * 136 + k]         = __float2bfloat16(hi);
        base[LTILE + f * 136 + k] = __float2bfloat16(w - hi);
    } else if (i < 98304 + 36864 + 9216) {  // dec repack
        int q = i - 135168;
        int br = q / 3072, r = q % 3072, m = r / 64, h = r % 64;
        dect[br * 6144 + m * 128 + h * 2]     = decW[br * 6144 + (2 * m) * 64 + h];
        dect[br * 6144 + m * 128 + h * 2 + 1] = decW[br * 6144 + (2 * m + 1) * 64 + h];
    }
}

// ---------------- graph kernels (round-7 proven) ----------------

__global__ void scatter6_all(const float* __restrict__ x0, const float* __restrict__ x1,
                             const float* __restrict__ x2,
                             const int* __restrict__ ei0, const int* __restrict__ ei1,
                             const int* __restrict__ ei2,
                             float* __restrict__ agg6) {
    int e = blockIdx.x * blockDim.x + threadIdx.x;
    if (e >= ETOT) return;
    int lvl = (e >= EB1) + (e >= EB2);
    const int* ei; const float* x; int le, E, nb;
    if (lvl == 0)      { ei = ei0; x = x0; le = e;       E = E0C; nb = 0;   }
    else if (lvl == 1) { ei = ei1; x = x1; le = e - EB1; E = E1C; nb = NB1; }
    else               { ei = ei2; x = x2; le = e - EB2; E = E2C; nb = NB2; }
    int s = ei[le];
    int d = ei[E + le];
    const float2* xs = (const float2*)(x + (size_t)s * 6);
    float2* a = (float2*)(agg6 + (size_t)(nb + d) * 6);
    float2 v0 = xs[0], v1 = xs[1], v2 = xs[2];
    atomicAdd(&a[0], v0);
    atomicAdd(&a[1], v1);
    atomicAdd(&a[2], v2);
}

#define C1_B0 1563
#define C1_B1 1954
__global__ void conv1_all(const float* __restrict__ x0, const float* __restrict__ x1,
                          const float* __restrict__ x2,
                          const float* __restrict__ agg6,
                          const float* __restrict__ Wrel, const float* __restrict__ brel,
                          const float* __restrict__ Wroot, float* __restrict__ h1) {
    __shared__ float sx[32 * 6];
    __shared__ float sa[32 * 6];
    int b = blockIdx.x;
    int lvl = (b >= C1_B0) + (b >= C1_B1);
    const float* x; int tb, nlv, nb;
    if (lvl == 0)      { x = x0; tb = 0;     nlv = N0; nb = 0;   }
    else if (lvl == 1) { x = x1; tb = C1_B0; nlv = N1; nb = NB1; }
    else               { x = x2; tb = C1_B1; nlv = N2; nb = NB2; }
    int base = (b - tb) * 32;
    int cnt = nlv - base; if (cnt > 32) cnt = 32;
    int t = threadIdx.x;
    for (int idx = t; idx < cnt * 6; idx += 128) {
        sx[idx] = x[(size_t)base * 6 + idx];
        sa[idx] = agg6[(size_t)(nb + base) * 6 + idx];
    }
    __syncthreads();
    const float* Wr = Wrel + lvl * 6 * 128;
    const float* Wo = Wroot + lvl * 6 * 128;
    float wrel[6], wroot[6];
#pragma unroll
    for (int k = 0; k < 6; k++) { wrel[k] = Wr[k * 128 + t]; wroot[k] = Wo[k * 128 + t]; }
    float bb = brel[lvl * 128 + t];
    for (int j = 0; j < cnt; j++) {
        float acc = bb;
#pragma unroll
        for (int k = 0; k < 6; k++)
            acc = fmaf(sa[j * 6 + k], wrel[k], fmaf(sx[j * 6 + k], wroot[k], acc));
        h1[(size_t)(nb + base + j) * 128 + t] = fmaxf(acc, 0.f);
    }
}

__global__ void scatter128_all(const float* __restrict__ h1,
                               const int* __restrict__ ei0, const int* __restrict__ ei1,
                               const int* __restrict__ ei2,
                               float* __restrict__ agg) {
    int w = (blockIdx.x * blockDim.x + threadIdx.x) >> 5;
    int lane = threadIdx.x & 31;
    int e0 = w * 4;
    if (e0 >= ETOT) return;
    int lvl = (e0 >= EB1) + (e0 >= EB2);
    const int* ei; int le, E, nb;
    if (lvl == 0)      { ei = ei0; le = e0;       E = E0C; nb = 0;   }
    else if (lvl == 1) { ei = ei1; le = e0 - EB1; E = E1C; nb = NB1; }
    else               { ei = ei2; le = e0 - EB2; E = E2C; nb = NB2; }
    int s[4], d[4];
#pragma unroll
    for (int i = 0; i < 4; i++) { s[i] = ei[le + i]; d[i] = ei[E + le + i]; }
    float4 v[4];
#pragma unroll
    for (int i = 0; i < 4; i++)
        v[i] = *(const float4*)(h1 + (size_t)(nb + s[i]) * 128 + lane * 4);
#pragma unroll
    for (int i = 0; i < 4; i++)
        atomicAdd((float4*)(agg + (size_t)(nb + d[i]) * 128 + lane * 4), v[i]);
}

// ---------------- conv2 + lin via mma.sync bf16 (split hi/lo, 3-term) ----------------
// smem: sA = 4 tiles 128x136 bf16 [agg_hi|agg_lo|h1_hi|h1_lo]; sW = 2 tiles (staged)
#define SMEM_MMA 208896     // (4*17408 + 2*17408)*2 bytes
#define CL_B0 391
#define CL_B1 489           // +25 -> 514 blocks
__global__ void __launch_bounds__(256, 1) conv2lin_mma(
    const float* __restrict__ agg, const float* __restrict__ h1,
    const __nv_bfloat16* __restrict__ wblob,
    const float* __restrict__ c2b, const float* __restrict__ linb,
    float* __restrict__ e) {
    extern __shared__ __nv_bfloat16 sm[];
    __nv_bfloat16* sA = sm;                 // 4*17408 elems
    __nv_bfloat16* sW = sm + 4 * WTILE;     // 2*17408 elems
    int t = threadIdx.x, lane = t & 31, wid = t >> 5;
    int wm = wid & 3, wn = wid >> 2;
    int b = blockIdx.x;
    int lvl = (b >= CL_B0) + (b >= CL_B1);
    int tb, nlv, nb0;
    if (lvl == 0)      { tb = 0;     nlv = N0; nb0 = 0;   }
    else if (lvl == 1) { tb = CL_B0; nlv = N1; nb0 = NB1; }
    else               { tb = CL_B1; nlv = N2; nb0 = NB2; }
    int base = (b - tb) * 128;
    int cnt = nlv - base; if (cnt > 128) cnt = 128;

    // stage activations: split fp32 -> bf16 hi/lo into padded tiles
    for (int idx = t; idx < 4096; idx += 256) {
        int row = idx >> 5, g = (idx & 31) * 4;
        bool v = row < cnt;
        size_t grow = (size_t)(nb0 + base + row) * 128 + g;
        float4 qa = v ? *(const float4*)(agg + grow) : make_float4(0.f, 0.f, 0.f, 0.f);
        float4 qh = v ? *(const float4*)(h1 + grow)  : make_float4(0.f, 0.f, 0.f, 0.f);
        float ax = bf16rn(qa.x), ay = bf16rn(qa.y), az = bf16rn(qa.z), aw = bf16rn(qa.w);
        float hx = bf16rn(qh.x), hy = bf16rn(qh.y), hz = bf16rn(qh.z), hw = bf16rn(qh.w);
        int off = row * 136 + g;
        *(uint2*)(sA + off) =
            make_uint2(pack_bf16x2(ax, ay), pack_bf16x2(az, aw));
        *(uint2*)(sA + WTILE + off) =
            make_uint2(pack_bf16x2(qa.x - ax, qa.y - ay), pack_bf16x2(qa.z - az, qa.w - aw));
        *(uint2*)(sA + 2 * WTILE + off) =
            make_uint2(pack_bf16x2(hx, hy), pack_bf16x2(hz, hw));
        *(uint2*)(sA + 3 * WTILE + off) =
            make_uint2(pack_bf16x2(qh.x - hx, qh.y - hy), pack_bf16x2(qh.z - hz, qh.w - hw));
    }
    // stage conv chunk0 weights (W1h|W1l)
    const uint4* wsrc = (const uint4*)(wblob + (size_t)lvl * WB_LVL);
    uint4* wdst = (uint4*)sW;
    for (int idx = t; idx < 4352; idx += 256) wdst[idx] = wsrc[idx];
    __syncthreads();

    // conv accumulators initialized with bias
    float acc[2][8][4];
#pragma unroll
    for (int nt = 0; nt < 8; nt++) {
        int c0 = wn * 64 + nt * 8 + (lane & 3) * 2;
        float b0v = c2b[lvl * 128 + c0];
        float b1v = c2b[lvl * 128 + c0 + 1];
#pragma unroll
        for (int mt = 0; mt < 2; mt++) {
            acc[mt][nt][0] = b0v; acc[mt][nt][1] = b1v;
            acc[mt][nt][2] = b0v; acc[mt][nt][3] = b1v;
        }
    }
    // chunk0 sections: Ah*Wh, Ah*Wl, Al*Wh
    run_section<8>(acc, sA,         sW,         wm, wn * 64, lane);
    run_section<8>(acc, sA,         sW + WTILE, wm, wn * 64, lane);
    run_section<8>(acc, sA + WTILE, sW,         wm, wn * 64, lane);
    __syncthreads();
    // stage chunk1 weights (W2h|W2l)
    for (int idx = t; idx < 4352; idx += 256) wdst[idx] = wsrc[4352 + idx];
    __syncthreads();
    run_section<8>(acc, sA + 2 * WTILE, sW,         wm, wn * 64, lane);
    run_section<8>(acc, sA + 2 * WTILE, sW + WTILE, wm, wn * 64, lane);
    run_section<8>(acc, sA + 3 * WTILE, sW,         wm, wn * 64, lane);
    __syncthreads();

    // epilogue 1: h2 = relu(acc) -> bf16 hi/lo into sA tiles 0 (hi), 1 (lo)
#pragma unroll
    for (int mt = 0; mt < 2; mt++) {
        int r0 = wm * 32 + mt * 16 + (lane >> 2);
#pragma unroll
        for (int nt = 0; nt < 8; nt++) {
            int c0 = wn * 64 + nt * 8 + (lane & 3) * 2;
            float v0 = fmaxf(acc[mt][nt][0], 0.f);
            float v1 = fmaxf(acc[mt][nt][1], 0.f);
            float v2 = fmaxf(acc[mt][nt][2], 0.f);
            float v3 = fmaxf(acc[mt][nt][3], 0.f);
            float h0 = bf16rn(v0), h1v = bf16rn(v1), h2v = bf16rn(v2), h3 = bf16rn(v3);
            *(unsigned*)(sA + r0 * 136 + c0)               = pack_bf16x2(h0, h1v);
            *(unsigned*)(sA + WTILE + r0 * 136 + c0)       = pack_bf16x2(v0 - h0, v1 - h1v);
            *(unsigned*)(sA + (r0 + 8) * 136 + c0)         = pack_bf16x2(h2v, h3);
            *(unsigned*)(sA + WTILE + (r0 + 8) * 136 + c0) = pack_bf16x2(v2 - h2v, v3 - h3);
        }
    }
    __syncthreads();
    // stage lin weights (Lh|Ll)
    for (int idx = t; idx < 3264; idx += 256) wdst[idx] = wsrc[8704 + idx];
    __syncthreads();

    // lin: N=96, warp tile 32x48 (6 n-tiles)
    float acc2[2][6][4];
#pragma unroll
    for (int nt = 0; nt < 6; nt++) {
        int c0 = wn * 48 + nt * 8 + (lane & 3) * 2;
        float b0v = linb[lvl * 96 + c0];
        float b1v = linb[lvl * 96 + c0 + 1];
#pragma unroll
        for (int mt = 0; mt < 2; mt++) {
            acc2[mt][nt][0] = b0v; acc2[mt][nt][1] = b1v;
            acc2[mt][nt][2] = b0v; acc2[mt][nt][3] = b1v;
        }
    }
    run_section<6>(acc2, sA,         sW,         wm, wn * 48, lane);
    run_section<6>(acc2, sA,         sW + LTILE, wm, wn * 48, lane);
    run_section<6>(acc2, sA + WTILE, sW,         wm, wn * 48, lane);

    // epilogue 2: e = acc2
#pragma unroll
    for (int mt = 0; mt < 2; mt++) {
        int r0 = wm * 32 + mt * 16 + (lane >> 2);
#pragma unroll
        for (int nt = 0; nt < 6; nt++) {
            int c0 = wn * 48 + nt * 8 + (lane & 3) * 2;
            if (r0 < cnt)
                *(float2*)(e + (size_t)(nb0 + base + r0) * 96 + c0) =
                    make_float2(acc2[mt][nt][0], acc2[mt][nt][1]);
            if (r0 + 8 < cnt)
                *(float2*)(e + (size_t)(nb0 + base + r0 + 8) * 96 + c0) =
                    make_float2(acc2[mt][nt][2], acc2[mt][nt][3]);
        }
    }
}

// ---------------- interp + dec (round-7 proven) ----------------

__global__ void interp_both(const float* __restrict__ e,
                            const int* __restrict__ A1r, const int* __restrict__ A1c,
                            const float* __restrict__ A1v,
                            const int* __restrict__ A2r, const int* __restrict__ A2c,
                            const float* __restrict__ A2v,
                            float* __restrict__ i1, float* __restrict__ i2) {
    int w = (blockIdx.x * blockDim.x + threadIdx.x) >> 5;
    int lane = threadIdx.x & 31;
    int q0 = w * 4;
    if (q0 >= 2 * NNZC) return;
    const int* Ar; const int* Ac; const float* Av; const float* ebase; float* dst; int off;
    if (q0 < NNZC) { Ar = A1r; Ac = A1c; Av = A1v;
                     ebase = e + (size_t)NB1 * 96; dst = i1; off = q0; }
    else           { Ar = A2r; Ac = A2c; Av = A2v;
                     ebase = e + (size_t)NB2 * 96; dst = i2; off = q0 - NNZC; }
    int r[4], c[4]; float v[4];
#pragma unroll
    for (int i = 0; i < 4; i++) { r[i] = Ar[off + i]; c[i] = Ac[off + i]; v[i] = Av[off + i]; }
    if (lane < 24) {
        float4 x[4];
#pragma unroll
        for (int i = 0; i < 4; i++)
            x[i] = *(const float4*)(ebase + (size_t)c[i] * 96 + lane * 4);
#pragma unroll
        for (int i = 0; i < 4; i++) {
            float4 y = make_float4(x[i].x * v[i], x[i].y * v[i], x[i].z * v[i], x[i].w * v[i]);
            atomicAdd((float4*)(dst + (size_t)r[i] * 96 + lane * 4), y);
        }
    }
}

__global__ void __launch_bounds__(256) dec_gemm_kernel(
    const float* __restrict__ e0, const float* __restrict__ i1,
    const float* __restrict__ i2,
    const float* __restrict__ dect, const float* __restrict__ b0,
    const float* __restrict__ Wout, const float* __restrict__ bout,
    float* __restrict__ out, int n) {
    extern __shared__ float sin_[];
    int base = blockIdx.x * 128;
    int cnt = n - base; if (cnt > 128) cnt = 128;
    int t = threadIdx.x;
    int lane = t & 31;
    int nb = (t >> 5) * 16;
#pragma unroll
    for (int br = 0; br < 3; br++) {
        __syncthreads();
        for (int idx = t; idx < cnt * 24; idx += 256) {
            int node = idx / 24, q = idx % 24;
            const float* srcp =
                (q < 8)  ? (e0 + (size_t)(base + node) * 96 + br * 32 + q * 4) :
                (q < 16) ? (i1 + (size_t)(base + node) * 96 + br * 32 + (q - 8) * 4) :
                           (i2 + (size_t)(base + node) * 96 + br * 32 + (q - 16) * 4);
            *(float4*)(sin_ + node * 96 + q * 4) = *(const float4*)srcp;
        }
        __syncthreads();
        const float* W = dect + br * 6144;
        float2 bb = *(const float2*)(b0 + br * 64 + 2 * lane);
        ull acc0[16], acc1[16];
        ull b0p = pk2(bb.x, 0.f), b1p = pk2(bb.y, 0.f);
#pragma unroll
        for (int j = 0; j < 16; j++) { acc0[j] = b0p; acc1[j] = b1p; }
        for (int m = 0; m < 48; m += 2) {
            ulonglong2 wA = *(const ulonglong2*)(W + m * 128 + lane * 4);
            ulonglong2 wB = *(const ulonglong2*)(W + (m + 1) * 128 + lane * 4);
#pragma unroll
            for (int j = 0; j < 16; j++) {
                ulonglong2 a = *(const ulonglong2*)(sin_ + (nb + j) * 96 + 2 * m);
                acc0[j] = fma2(a.x, wA.x, acc0[j]);
                acc1[j] = fma2(a.x, wA.y, acc1[j]);
                acc0[j] = fma2(a.y, wB.x, acc0[j]);
                acc1[j] = fma2(a.y, wB.y, acc1[j]);
            }
        }
        float2 wo = *(const float2*)(Wout + br * 64 + 2 * lane);
        float bo = bout[br];
#pragma unroll
        for (int j = 0; j < 16; j++) {
            float h0 = hsum2(acc0[j]);
            float h1 = hsum2(acc1[j]);
            h0 = h0 > 0.f ? h0 : expm1f(h0);
            h1 = h1 > 0.f ? h1 : expm1f(h1);
            float r = fmaf(h0, wo.x, h1 * wo.y);
#pragma unroll
            for (int s = 16; s > 0; s >>= 1)
                r += __shfl_xor_sync(0xffffffffu, r, s);
            if (lane == 0 && nb + j < cnt)
                out[(size_t)(base + nb + j) * 3 + br] = r + bo;
        }
    }
}

// ---------------- host orchestration: 7 launches ----------------

extern "C" void kernel_launch(void* const* d_in, const int* in_sizes, int n_in,
                              void* d_out, int out_size) {
    const float* x0 = (const float*)d_in[0];
    const float* x1 = (const float*)d_in[1];
    const float* x2 = (const float*)d_in[2];
    const int* ei0 = (const int*)d_in[3];
    const int* ei1 = (const int*)d_in[4];
    const int* ei2 = (const int*)d_in[5];
    const int*   A1r = (const int*)d_in[6];
    const int*   A1c = (const int*)d_in[7];
    const float* A1v = (const float*)d_in[8];
    const int*   A2r = (const int*)d_in[9];
    const int*   A2c = (const int*)d_in[10];
    const float* A2v = (const float*)d_in[11];
    const float* c1Wrel  = (const float*)d_in[12];
    const float* c1brel  = (const float*)d_in[13];
    const float* c1Wroot = (const float*)d_in[14];
    const float* c2Wrel  = (const float*)d_in[15];
    const float* c2brel  = (const float*)d_in[16];
    const float* c2Wroot = (const float*)d_in[17];
    const float* linW = (const float*)d_in[18];
    const float* linb = (const float*)d_in[19];
    const float* dW0   = (const float*)d_in[20];
    const float* db0   = (const float*)d_in[21];
    const float* dWout = (const float*)d_in[22];
    const float* dbout = (const float*)d_in[23];
    float* out = (float*)d_out;

    void* p;
    cudaGetSymbolAddress(&p, g_zr);    float* zr = (float*)p;
    cudaGetSymbolAddress(&p, g_h1);    float* h1 = (float*)p;
    cudaGetSymbolAddress(&p, g_e);     float* e  = (float*)p;
    cudaGetSymbolAddress(&p, g_dect);  float* dect = (float*)p;
    cudaGetSymbolAddress(&p, g_wblob); __nv_bfloat16* wblob = (__nv_bfloat16*)p;
    float* agg6 = zr + AGG6_OFF;
    float* agg  = zr + AGG_OFF;
    float* i1b  = zr + I1_OFF;
    float* i2b  = zr + I2_OFF;

    cudaFuncSetAttribute(conv2lin_mma, cudaFuncAttributeMaxDynamicSharedMemorySize, SMEM_MMA);
    cudaFuncSetAttribute(dec_gemm_kernel, cudaFuncAttributeMaxDynamicSharedMemorySize, 49152);

    prep_kernel<<<cdiv(ZR_TOT / 4, 256), 256>>>(c2Wrel, c2Wroot, linW, dW0,
                                                wblob, dect, (float4*)zr, ZR_TOT / 4);
    scatter6_all<<<cdiv(ETOT, 256), 256>>>(x0, x1, x2, ei0, ei1, ei2, agg6);
    conv1_all<<<C1_B1 + 98, 128>>>(x0, x1, x2, agg6, c1Wrel, c1brel, c1Wroot, h1);
    scatter128_all<<<cdiv((ETOT / 4) * 32, 256), 256>>>(h1, ei0, ei1, ei2, agg);
    conv2lin_mma<<<CL_B1 + 25, 256, SMEM_MMA>>>(agg, h1, wblob, c2brel, linb, e);
    interp_both<<<cdiv((2 * NNZC / 4) * 32, 256), 256>>>(e, A1r, A1c, A1v,
                                                         A2r, A2c, A2v, i1b, i2b);
    dec_gemm_kernel<<<cdiv(N0, 128), 256, 49152>>>(e, i1b, i2b, dect, db0,
                                                   dWout, dbout, out, N0);
}

// round 10
// speedup vs baseline: 1.5431x; 1.2424x over previous
#include <cuda_runtime.h>
#include <cuda_bf16.h>
#include <math.h>

#define N0 50000
#define N1 12500
#define N2 3125
#define NTOT 65625
#define E0C 800000
#define E1C 200000
#define E2C 50000
#define ETOT 1050000
#define NNZC 200000

#define NB1 50000
#define NB2 62500
#define EB1 800000
#define EB2 1000000

// -------- fused zeroed scratch region: [agg6 | agg | i1 | i2] --------
#define AGG6_OFF 0
#define AGG_OFF  393752
#define I1_OFF   8793752
#define I2_OFF   13593752
#define ZR_TOT   18393752

__device__ float g_zr[ZR_TOT];
__device__ __align__(16) float g_h1[NTOT * 128];
__device__ float g_e [NTOT * 96];
// per-level bf16 weight blob: [W1h|W1l|W2h|W2l] 4x(128x136) + [Lh|Ll] 2x(96x136)
#define WTILE 17408            // 128*136 bf16 elems
#define LTILE 13056            // 96*136
#define WB_LVL 95744
__device__ __align__(16) __nv_bfloat16 g_wblob[3 * WB_LVL];
// dec blob: per branch [64n x 104k] hi + lo
#define DTILE 6656             // 64*104
#define DB_BR 13312            // 2*DTILE
__device__ __align__(16) __nv_bfloat16 g_dblob[3 * DB_BR];

static inline int cdiv(int a, int b) { return (a + b - 1) / b; }

// ---------------- bf16 helpers ----------------
__device__ __forceinline__ unsigned pack_bf16x2(float lo_f, float hi_f) {
    unsigned r;
    asm("cvt.rn.bf16x2.f32 %0, %1, %2;" : "=r"(r) : "f"(hi_f), "f"(lo_f));
    return r;
}
__device__ __forceinline__ float bf16rn(float x) {
    return __bfloat162float(__float2bfloat16(x));
}

// mma.sync m16n8k16 bf16 (baseline sm_80+ feature)
__device__ __forceinline__ void mma_bf16(float c[4], const unsigned a[4],
                                         unsigned b0, unsigned b1) {
    asm volatile(
        "mma.sync.aligned.m16n8k16.row.col.f32.bf16.bf16.f32 "
        "{%0,%1,%2,%3}, {%4,%5,%6,%7}, {%8,%9}, {%0,%1,%2,%3};"
        : "+f"(c[0]), "+f"(c[1]), "+f"(c[2]), "+f"(c[3])
        : "r"(a[0]), "r"(a[1]), "r"(a[2]), "r"(a[3]), "r"(b0), "r"(b1));
}

// K-section over padded tiles: acc[2][NT][4] += A(Mx*, STRIDE) @ B^T
template<int NT, int KSTEPS, int STRIDE>
__device__ __forceinline__ void run_section(
    float (*acc)[NT][4],
    const __nv_bfloat16* __restrict__ At, const __nv_bfloat16* __restrict__ Wt,
    int wm, int wn_base, int lane) {
    int rbase = wm * 32 + (lane >> 2);
    int kc = (lane & 3) * 2;
#pragma unroll
    for (int ks = 0; ks < KSTEPS; ks++) {
        int k0 = ks * 16 + kc;
        unsigned a[2][4];
#pragma unroll
        for (int mt = 0; mt < 2; mt++) {
            const __nv_bfloat16* p = At + (rbase + mt * 16) * STRIDE + k0;
            a[mt][0] = *(const unsigned*)p;
            a[mt][1] = *(const unsigned*)(p + 8 * STRIDE);
            a[mt][2] = *(const unsigned*)(p + 8);
            a[mt][3] = *(const unsigned*)(p + 8 * STRIDE + 8);
        }
#pragma unroll
        for (int nt = 0; nt < NT; nt++) {
            const __nv_bfloat16* q = Wt + (wn_base + nt * 8 + (lane >> 2)) * STRIDE + k0;
            unsigned b0 = *(const unsigned*)q;
            unsigned b1 = *(const unsigned*)(q + 8);
            mma_bf16(acc[0][nt], a[0], b0, b1);
            mma_bf16(acc[1][nt], a[1], b0, b1);
        }
    }
}

// ---------------- prep: zero + bf16 split-transpose weights ----------------
__global__ void prep_kernel(const float* __restrict__ W1, const float* __restrict__ W2,
                            const float* __restrict__ linW, const float* __restrict__ decW,
                            __nv_bfloat16* __restrict__ wblob,
                            __nv_bfloat16* __restrict__ dblob,
                            float4* __restrict__ zr, int nq) {
    int i = blockIdx.x * blockDim.x + threadIdx.x;
    if (i < nq) zr[i] = make_float4(0.f, 0.f, 0.f, 0.f);
    if (i < 98304) {                        // conv2: 3 lvl x 2 chunk x 128k x 128f
        int lvl = i / 32768, r = i % 32768;
        int chunk = r / 16384, q = r % 16384;
        int k = q / 128, f = q % 128;
        float w = (chunk == 0 ? W1 : W2)[lvl * 16384 + k * 128 + f];
        float hi = bf16rn(w);
        __nv_bfloat16* base = wblob + lvl * WB_LVL + chunk * 2 * WTILE;
        base[f * 136 + k]         = __float2bfloat16(hi);
        base[WTILE + f * 136 + k] = __float2bfloat16(w - hi);
    } else if (i < 98304 + 36864) {         // lin: 3 lvl x 128k x 96f
        int q = i - 98304;
        int lvl = q / 12288, r = q % 12288;
        int k = r / 96, f = r % 96;
        float w = linW[lvl * 12288 + k * 96 + f];
        float hi = bf16rn(w);
        __nv_bfloat16* base = wblob + lvl * WB_LVL + 4 * WTILE;
        base[f * 136 + k]         = __float2bfloat16(hi);
        base[LTILE + f * 136 + k] = __float2bfloat16(w - hi);
    } else if (i < 98304 + 36864 + 18432) { // dec: 3 br x 96k x 64n -> [n][k] hi/lo
        int q = i - 135168;
        int br = q / 6144, r = q % 6144, k = r / 64, n = r % 64;
        float w = decW[br * 6144 + k * 64 + n];
        float hi = bf16rn(w);
        __nv_bfloat16* base = dblob + br * DB_BR;
        base[n * 104 + k]         = __float2bfloat16(hi);
        base[DTILE + n * 104 + k] = __float2bfloat16(w - hi);
    }
}

// ---------------- graph kernels (proven) ----------------

__global__ void scatter6_all(const float* __restrict__ x0, const float* __restrict__ x1,
                             const float* __restrict__ x2,
                             const int* __restrict__ ei0, const int* __restrict__ ei1,
                             const int* __restrict__ ei2,
                             float* __restrict__ agg6) {
    int e = blockIdx.x * blockDim.x + threadIdx.x;
    if (e >= ETOT) return;
    int lvl = (e >= EB1) + (e >= EB2);
    const int* ei; const float* x; int le, E, nb;
    if (lvl == 0)      { ei = ei0; x = x0; le = e;       E = E0C; nb = 0;   }
    else if (lvl == 1) { ei = ei1; x = x1; le = e - EB1; E = E1C; nb = NB1; }
    else               { ei = ei2; x = x2; le = e - EB2; E = E2C; nb = NB2; }
    int s = ei[le];
    int d = ei[E + le];
    const float2* xs = (const float2*)(x + (size_t)s * 6);
    float2* a = (float2*)(agg6 + (size_t)(nb + d) * 6);
    float2 v0 = xs[0], v1 = xs[1], v2 = xs[2];
    atomicAdd(&a[0], v0);
    atomicAdd(&a[1], v1);
    atomicAdd(&a[2], v2);
}

#define C1_B0 1563
#define C1_B1 1954
__global__ void conv1_all(const float* __restrict__ x0, const float* __restrict__ x1,
                          const float* __restrict__ x2,
                          const float* __restrict__ agg6,
                          const float* __restrict__ Wrel, const float* __restrict__ brel,
                          const float* __restrict__ Wroot, float* __restrict__ h1) {
    __shared__ float sx[32 * 6];
    __shared__ float sa[32 * 6];
    int b = blockIdx.x;
    int lvl = (b >= C1_B0) + (b >= C1_B1);
    const float* x; int tb, nlv, nb;
    if (lvl == 0)      { x = x0; tb = 0;     nlv = N0; nb = 0;   }
    else if (lvl == 1) { x = x1; tb = C1_B0; nlv = N1; nb = NB1; }
    else               { x = x2; tb = C1_B1; nlv = N2; nb = NB2; }
    int base = (b - tb) * 32;
    int cnt = nlv - base; if (cnt > 32) cnt = 32;
    int t = threadIdx.x;
    for (int idx = t; idx < cnt * 6; idx += 128) {
        sx[idx] = x[(size_t)base * 6 + idx];
        sa[idx] = agg6[(size_t)(nb + base) * 6 + idx];
    }
    __syncthreads();
    const float* Wr = Wrel + lvl * 6 * 128;
    const float* Wo = Wroot + lvl * 6 * 128;
    float wrel[6], wroot[6];
#pragma unroll
    for (int k = 0; k < 6; k++) { wrel[k] = Wr[k * 128 + t]; wroot[k] = Wo[k * 128 + t]; }
    float bb = brel[lvl * 128 + t];
    for (int j = 0; j < cnt; j++) {
        float acc = bb;
#pragma unroll
        for (int k = 0; k < 6; k++)
            acc = fmaf(sa[j * 6 + k], wrel[k], fmaf(sx[j * 6 + k], wroot[k], acc));
        h1[(size_t)(nb + base + j) * 128 + t] = fmaxf(acc, 0.f);
    }
}

__global__ void scatter128_all(const float* __restrict__ h1,
                               const int* __restrict__ ei0, const int* __restrict__ ei1,
                               const int* __restrict__ ei2,
                               float* __restrict__ agg) {
    int w = (blockIdx.x * blockDim.x + threadIdx.x) >> 5;
    int lane = threadIdx.x & 31;
    int e0 = w * 4;
    if (e0 >= ETOT) return;
    int lvl = (e0 >= EB1) + (e0 >= EB2);
    const int* ei; int le, E, nb;
    if (lvl == 0)      { ei = ei0; le = e0;       E = E0C; nb = 0;   }
    else if (lvl == 1) { ei = ei1; le = e0 - EB1; E = E1C; nb = NB1; }
    else               { ei = ei2; le = e0 - EB2; E = E2C; nb = NB2; }
    int s[4], d[4];
#pragma unroll
    for (int i = 0; i < 4; i++) { s[i] = ei[le + i]; d[i] = ei[E + le + i]; }
    float4 v[4];
#pragma unroll
    for (int i = 0; i < 4; i++)
        v[i] = *(const float4*)(h1 + (size_t)(nb + s[i]) * 128 + lane * 4);
#pragma unroll
    for (int i = 0; i < 4; i++)
        atomicAdd((float4*)(agg + (size_t)(nb + d[i]) * 128 + lane * 4), v[i]);
}

// ---------------- conv2 + lin via mma.sync bf16 (round-9 proven) ----------------
#define SMEM_MMA 208896
#define CL_B0 391
#define CL_B1 489
__global__ void __launch_bounds__(256, 1) conv2lin_mma(
    const float* __restrict__ agg, const float* __restrict__ h1,
    const __nv_bfloat16* __restrict__ wblob,
    const float* __restrict__ c2b, const float* __restrict__ linb,
    float* __restrict__ e) {
    extern __shared__ __nv_bfloat16 sm[];
    __nv_bfloat16* sA = sm;
    __nv_bfloat16* sW = sm + 4 * WTILE;
    int t = threadIdx.x, lane = t & 31, wid = t >> 5;
    int wm = wid & 3, wn = wid >> 2;
    int b = blockIdx.x;
    int lvl = (b >= CL_B0) + (b >= CL_B1);
    int tb, nlv, nb0;
    if (lvl == 0)      { tb = 0;     nlv = N0; nb0 = 0;   }
    else if (lvl == 1) { tb = CL_B0; nlv = N1; nb0 = NB1; }
    else               { tb = CL_B1; nlv = N2; nb0 = NB2; }
    int base = (b - tb) * 128;
    int cnt = nlv - base; if (cnt > 128) cnt = 128;

    for (int idx = t; idx < 4096; idx += 256) {
        int row = idx >> 5, g = (idx & 31) * 4;
        bool v = row < cnt;
        size_t grow = (size_t)(nb0 + base + row) * 128 + g;
        float4 qa = v ? *(const float4*)(agg + grow) : make_float4(0.f, 0.f, 0.f, 0.f);
        float4 qh = v ? *(const float4*)(h1 + grow)  : make_float4(0.f, 0.f, 0.f, 0.f);
        float ax = bf16rn(qa.x), ay = bf16rn(qa.y), az = bf16rn(qa.z), aw = bf16rn(qa.w);
        float hx = bf16rn(qh.x), hy = bf16rn(qh.y), hz = bf16rn(qh.z), hw = bf16rn(qh.w);
        int off = row * 136 + g;
        *(uint2*)(sA + off) =
            make_uint2(pack_bf16x2(ax, ay), pack_bf16x2(az, aw));
        *(uint2*)(sA + WTILE + off) =
            make_uint2(pack_bf16x2(qa.x - ax, qa.y - ay), pack_bf16x2(qa.z - az, qa.w - aw));
        *(uint2*)(sA + 2 * WTILE + off) =
            make_uint2(pack_bf16x2(hx, hy), pack_bf16x2(hz, hw));
        *(uint2*)(sA + 3 * WTILE + off) =
            make_uint2(pack_bf16x2(qh.x - hx, qh.y - hy), pack_bf16x2(qh.z - hz, qh.w - hw));
    }
    const uint4* wsrc = (const uint4*)(wblob + (size_t)lvl * WB_LVL);
    uint4* wdst = (uint4*)sW;
    for (int idx = t; idx < 4352; idx += 256) wdst[idx] = wsrc[idx];
    __syncthreads();

    float acc[2][8][4];
#pragma unroll
    for (int nt = 0; nt < 8; nt++) {
        int c0 = wn * 64 + nt * 8 + (lane & 3) * 2;
        float b0v = c2b[lvl * 128 + c0];
        float b1v = c2b[lvl * 128 + c0 + 1];
#pragma unroll
        for (int mt = 0; mt < 2; mt++) {
            acc[mt][nt][0] = b0v; acc[mt][nt][1] = b1v;
            acc[mt][nt][2] = b0v; acc[mt][nt][3] = b1v;
        }
    }
    run_section<8, 8, 136>(acc, sA,         sW,         wm, wn * 64, lane);
    run_section<8, 8, 136>(acc, sA,         sW + WTILE, wm, wn * 64, lane);
    run_section<8, 8, 136>(acc, sA + WTILE, sW,         wm, wn * 64, lane);
    __syncthreads();
    for (int idx = t; idx < 4352; idx += 256) wdst[idx] = wsrc[4352 + idx];
    __syncthreads();
    run_section<8, 8, 136>(acc, sA + 2 * WTILE, sW,         wm, wn * 64, lane);
    run_section<8, 8, 136>(acc, sA + 2 * WTILE, sW + WTILE, wm, wn * 64, lane);
    run_section<8, 8, 136>(acc, sA + 3 * WTILE, sW,         wm, wn * 64, lane);
    __syncthreads();

#pragma unroll
    for (int mt = 0; mt < 2; mt++) {
        int r0 = wm * 32 + mt * 16 + (lane >> 2);
#pragma unroll
        for (int nt = 0; nt < 8; nt++) {
            int c0 = wn * 64 + nt * 8 + (lane & 3) * 2;
            float v0 = fmaxf(acc[mt][nt][0], 0.f);
            float v1 = fmaxf(acc[mt][nt][1], 0.f);
            float v2 = fmaxf(acc[mt][nt][2], 0.f);
            float v3 = fmaxf(acc[mt][nt][3], 0.f);
            float h0 = bf16rn(v0), h1v = bf16rn(v1), h2v = bf16rn(v2), h3 = bf16rn(v3);
            *(unsigned*)(sA + r0 * 136 + c0)               = pack_bf16x2(h0, h1v);
            *(unsigned*)(sA + WTILE + r0 * 136 + c0)       = pack_bf16x2(v0 - h0, v1 - h1v);
            *(unsigned*)(sA + (r0 + 8) * 136 + c0)         = pack_bf16x2(h2v, h3);
            *(unsigned*)(sA + WTILE + (r0 + 8) * 136 + c0) = pack_bf16x2(v2 - h2v, v3 - h3);
        }
    }
    __syncthreads();
    for (int idx = t; idx < 3264; idx += 256) wdst[idx] = wsrc[8704 + idx];
    __syncthreads();

    float acc2[2][6][4];
#pragma unroll
    for (int nt = 0; nt < 6; nt++) {
        int c0 = wn * 48 + nt * 8 + (lane & 3) * 2;
        float b0v = linb[lvl * 96 + c0];
        float b1v = linb[lvl * 96 + c0 + 1];
#pragma unroll
        for (int mt = 0; mt < 2; mt++) {
            acc2[mt][nt][0] = b0v; acc2[mt][nt][1] = b1v;
            acc2[mt][nt][2] = b0v; acc2[mt][nt][3] = b1v;
        }
    }
    run_section<6, 8, 136>(acc2, sA,         sW,         wm, wn * 48, lane);
    run_section<6, 8, 136>(acc2, sA,         sW + LTILE, wm, wn * 48, lane);
    run_section<6, 8, 136>(acc2, sA + WTILE, sW,         wm, wn * 48, lane);

#pragma unroll
    for (int mt = 0; mt < 2; mt++) {
        int r0 = wm * 32 + mt * 16 + (lane >> 2);
#pragma unroll
        for (int nt = 0; nt < 6; nt++) {
            int c0 = wn * 48 + nt * 8 + (lane & 3) * 2;
            if (r0 < cnt)
                *(float2*)(e + (size_t)(nb0 + base + r0) * 96 + c0) =
                    make_float2(acc2[mt][nt][0], acc2[mt][nt][1]);
            if (r0 + 8 < cnt)
                *(float2*)(e + (size_t)(nb0 + base + r0 + 8) * 96 + c0) =
                    make_float2(acc2[mt][nt][2], acc2[mt][nt][3]);
        }
    }
}

// ---------------- interp (proven) ----------------

__global__ void interp_both(const float* __restrict__ e,
                            const int* __restrict__ A1r, const int* __restrict__ A1c,
                            const float* __restrict__ A1v,
                            const int* __restrict__ A2r, const int* __restrict__ A2c,
                            const float* __restrict__ A2v,
                            float* __restrict__ i1, float* __restrict__ i2) {
    int w = (blockIdx.x * blockDim.x + threadIdx.x) >> 5;
    int lane = threadIdx.x & 31;
    int q0 = w * 4;
    if (q0 >= 2 * NNZC) return;
    const int* Ar; const int* Ac; const float* Av; const float* ebase; float* dst; int off;
    if (q0 < NNZC) { Ar = A1r; Ac = A1c; Av = A1v;
                     ebase = e + (size_t)NB1 * 96; dst = i1; off = q0; }
    else           { Ar = A2r; Ac = A2c; Av = A2v;
                     ebase = e + (size_t)NB2 * 96; dst = i2; off = q0 - NNZC; }
    int r[4], c[4]; float v[4];
#pragma unroll
    for (int i = 0; i < 4; i++) { r[i] = Ar[off + i]; c[i] = Ac[off + i]; v[i] = Av[off + i]; }
    if (lane < 24) {
        float4 x[4];
#pragma unroll
        for (int i = 0; i < 4; i++)
            x[i] = *(const float4*)(ebase + (size_t)c[i] * 96 + lane * 4);
#pragma unroll
        for (int i = 0; i < 4; i++) {
            float4 y = make_float4(x[i].x * v[i], x[i].y * v[i], x[i].z * v[i], x[i].w * v[i]);
            atomicAdd((float4*)(dst + (size_t)r[i] * 96 + lane * 4), y);
        }
    }
}

// ---------------- decoder via mma.sync bf16 (split hi/lo, 3-term) ----------------
// per branch: M=128 nodes, K=96 (e0|i1|i2 slices), N=64 hidden; elu; dot Wout.
// smem: sA hi/lo 128x104 (2x13312 elems), sW hi/lo 64x104 (2x6656), sdec[2][128]
#define SMEM_DEC (4 * 13312 + 2 * 13312 + 1024)   // bytes: 53248+26624+1024 = 80896
__global__ void __launch_bounds__(256, 1) dec_mma_kernel(
    const float* __restrict__ e0, const float* __restrict__ i1,
    const float* __restrict__ i2,
    const __nv_bfloat16* __restrict__ dblob, const float* __restrict__ b0,
    const float* __restrict__ Wout, const float* __restrict__ bout,
    float* __restrict__ out, int n) {
    extern __shared__ __nv_bfloat16 sm[];
    __nv_bfloat16* sA = sm;                    // hi 13312 | lo 13312
    __nv_bfloat16* sW = sm + 2 * 13312;        // hi 6656 | lo 6656
    float* sdec = (float*)(sm + 2 * 13312 + 2 * 6656);  // [2][128]
    int t = threadIdx.x, lane = t & 31, wid = t >> 5;
    int wm = wid & 3, wn = wid >> 2;
    int base = blockIdx.x * 128;
    int cnt = n - base; if (cnt > 128) cnt = 128;

#pragma unroll
    for (int br = 0; br < 3; br++) {
        __syncthreads();   // protect previous branch's smem reads
        // stage A: [128 rows][96 k] = e0|i1|i2 cols br*32..+31, split hi/lo
        for (int idx = t; idx < 128 * 24; idx += 256) {
            int row = idx / 24, q = idx % 24;
            const float* src = (q < 8) ? e0 : (q < 16) ? i1 : i2;
            int qq = q & 7;
            bool v = row < cnt;
            float4 x = v ? *(const float4*)(src + (size_t)(base + row) * 96 + br * 32 + qq * 4)
                         : make_float4(0.f, 0.f, 0.f, 0.f);
            float hx = bf16rn(x.x), hy = bf16rn(x.y), hz = bf16rn(x.z), hw = bf16rn(x.w);
            int off = row * 104 + q * 4;
            *(uint2*)(sA + off) = make_uint2(pack_bf16x2(hx, hy), pack_bf16x2(hz, hw));
            *(uint2*)(sA + 13312 + off) =
                make_uint2(pack_bf16x2(x.x - hx, x.y - hy), pack_bf16x2(x.z - hz, x.w - hw));
        }
        // stage W: branch blob (hi|lo contiguous, 13312 elems = 1664 uint4)
        {
            const uint4* wsrc = (const uint4*)(dblob + (size_t)br * DB_BR);
            uint4* wdst = (uint4*)sW;
            for (int idx = t; idx < 1664; idx += 256) wdst[idx] = wsrc[idx];
        }
        __syncthreads();

        // acc init with b0 bias
        float acc[2][4][4];
#pragma unroll
        for (int nt = 0; nt < 4; nt++) {
            int c0 = wn * 32 + nt * 8 + (lane & 3) * 2;
            float b0v = b0[br * 64 + c0];
            float b1v = b0[br * 64 + c0 + 1];
#pragma unroll
            for (int mt = 0; mt < 2; mt++) {
                acc[mt][nt][0] = b0v; acc[mt][nt][1] = b1v;
                acc[mt][nt][2] = b0v; acc[mt][nt][3] = b1v;
            }
        }
        run_section<4, 6, 104>(acc, sA,         sW,         wm, wn * 32, lane);
        run_section<4, 6, 104>(acc, sA,         sW + DTILE, wm, wn * 32, lane);
        run_section<4, 6, 104>(acc, sA + 13312, sW,         wm, wn * 32, lane);

        // epilogue: elu, dot with Wout over this warp's 32 cols, reduce
        float part[4] = {0.f, 0.f, 0.f, 0.f};  // rows r0 + {0,8,16,24}-ish per mt
#pragma unroll
        for (int nt = 0; nt < 4; nt++) {
            int c0 = wn * 32 + nt * 8 + (lane & 3) * 2;
            float w0 = Wout[br * 64 + c0];
            float w1 = Wout[br * 64 + c0 + 1];
#pragma unroll
            for (int mt = 0; mt < 2; mt++) {
                float h0 = acc[mt][nt][0] > 0.f ? acc[mt][nt][0] : expm1f(acc[mt][nt][0]);
                float h1 = acc[mt][nt][1] > 0.f ? acc[mt][nt][1] : expm1f(acc[mt][nt][1]);
                float h2 = acc[mt][nt][2] > 0.f ? acc[mt][nt][2] : expm1f(acc[mt][nt][2]);
                float h3 = acc[mt][nt][3] > 0.f ? acc[mt][nt][3] : expm1f(acc[mt][nt][3]);
                part[mt * 2]     += h0 * w0 + h1 * w1;   // row rbase + mt*16
                part[mt * 2 + 1] += h2 * w0 + h3 * w1;   // row rbase + mt*16 + 8
            }
        }
#pragma unroll
        for (int s = 1; s <= 2; s <<= 1) {
#pragma unroll
            for (int i = 0; i < 4; i++)
                part[i] += __shfl_xor_sync(0xffffffffu, part[i], s);
        }
        if ((lane & 3) == 0) {
            int r = wm * 32 + (lane >> 2);
            sdec[wn * 128 + r]      = part[0];
            sdec[wn * 128 + r + 16] = part[2];
            sdec[wn * 128 + r + 8]  = part[1];
            sdec[wn * 128 + r + 24] = part[3];
        }
        __syncthreads();
        if (t < 128 && t < cnt)
            out[(size_t)(base + t) * 3 + br] = sdec[t] + sdec[128 + t] + bout[br];
    }
}

// ---------------- host orchestration: 7 launches ----------------

extern "C" void kernel_launch(void* const* d_in, const int* in_sizes, int n_in,
                              void* d_out, int out_size) {
    const float* x0 = (const float*)d_in[0];
    const float* x1 = (const float*)d_in[1];
    const float* x2 = (const float*)d_in[2];
    const int* ei0 = (const int*)d_in[3];
    const int* ei1 = (const int*)d_in[4];
    const int* ei2 = (const int*)d_in[5];
    const int*   A1r = (const int*)d_in[6];
    const int*   A1c = (const int*)d_in[7];
    const float* A1v = (const float*)d_in[8];
    const int*   A2r = (const int*)d_in[9];
    const int*   A2c = (const int*)d_in[10];
    const float* A2v = (const float*)d_in[11];
    const float* c1Wrel  = (const float*)d_in[12];
    const float* c1brel  = (const float*)d_in[13];
    const float* c1Wroot = (const float*)d_in[14];
    const float* c2Wrel  = (const float*)d_in[15];
    const float* c2brel  = (const float*)d_in[16];
    const float* c2Wroot = (const float*)d_in[17];
    const float* linW = (const float*)d_in[18];
    const float* linb = (const float*)d_in[19];
    const float* dW0   = (const float*)d_in[20];
    const float* db0   = (const float*)d_in[21];
    const float* dWout = (const float*)d_in[22];
    const float* dbout = (const float*)d_in[23];
    float* out = (float*)d_out;

    void* p;
    cudaGetSymbolAddress(&p, g_zr);    float* zr = (float*)p;
    cudaGetSymbolAddress(&p, g_h1);    float* h1 = (float*)p;
    cudaGetSymbolAddress(&p, g_e);     float* e  = (float*)p;
    cudaGetSymbolAddress(&p, g_wblob); __nv_bfloat16* wblob = (__nv_bfloat16*)p;
    cudaGetSymbolAddress(&p, g_dblob); __nv_bfloat16* dblob = (__nv_bfloat16*)p;
    float* agg6 = zr + AGG6_OFF;
    float* agg  = zr + AGG_OFF;
    float* i1b  = zr + I1_OFF;
    float* i2b  = zr + I2_OFF;

    cudaFuncSetAttribute(conv2lin_mma, cudaFuncAttributeMaxDynamicSharedMemorySize, SMEM_MMA);
    cudaFuncSetAttribute(dec_mma_kernel, cudaFuncAttributeMaxDynamicSharedMemorySize, SMEM_DEC);

    prep_kernel<<<cdiv(ZR_TOT / 4, 256), 256>>>(c2Wrel, c2Wroot, linW, dW0,
                                                wblob, dblob, (float4*)zr, ZR_TOT / 4);
    scatter6_all<<<cdiv(ETOT, 256), 256>>>(x0, x1, x2, ei0, ei1, ei2, agg6);
    conv1_all<<<C1_B1 + 98, 128>>>(x0, x1, x2, agg6, c1Wrel, c1brel, c1Wroot, h1);
    scatter128_all<<<cdiv((ETOT / 4) * 32, 256), 256>>>(h1, ei0, ei1, ei2, agg);
    conv2lin_mma<<<CL_B1 + 25, 256, SMEM_MMA>>>(agg, h1, wblob, c2brel, linb, e);
    interp_both<<<cdiv((2 * NNZC / 4) * 32, 256), 256>>>(e, A1r, A1c, A1v,
                                                         A2r, A2c, A2v, i1b, i2b);
    dec_mma_kernel<<<cdiv(N0, 128), 256, SMEM_DEC>>>(e, i1b, i2b, dblob, db0,
                                                     dWout, dbout, out, N0);
}